// round 12
// baseline (speedup 1.0000x reference)
#include <cuda_runtime.h>
#include <cuda_fp16.h>
#include <cstdint>

// Problem constants
#define BD    8
#define TD    4096
#define DD    512
#define DIE   1024          // DI
#define NROWS (BD*TD)       // 32768
#define LN_EPS 1e-5f

// ---------------- scratch (no cudaMalloc allowed) ----------------
__device__ __half g_xzh[(size_t)NROWS * 2 * DIE];   // gemm1 out (fp16)
__device__ __half g_cfh[(size_t)NROWS * DIE];
__device__ __half g_cbh[(size_t)NROWS * DIE];
__device__ __half g_pfh[(size_t)NROWS * DIE];
__device__ __half g_pbh[(size_t)NROWS * DIE];
__device__ __half g_yh [(size_t)NROWS * DIE];
__device__ __half g_oh [(size_t)NROWS * DD];        // out_proj result (fp16)
__device__ __half g_xh [(size_t)NROWS * DD];        // fp16 x
__device__ __half g_w1h[(size_t)2 * DIE * DD];
__device__ __half g_wfh[(size_t)DIE * DIE];
__device__ __half g_wbh[(size_t)DIE * DIE];
__device__ __half g_woh[(size_t)DD * DIE];

__device__ __forceinline__ float silu_f(float v) {
    return v / (1.f + __expf(-v));
}

__device__ __forceinline__ uint32_t smem_to_u32(const void* p) {
    uint32_t a;
    asm("{ .reg .u64 t; cvta.to.shared.u64 t, %1; cvt.u32.u64 %0, t; }" : "=r"(a) : "l"(p));
    return a;
}

__device__ __forceinline__ void mma_f16(float* c, const uint32_t* a,
                                        uint32_t b0, uint32_t b1) {
    asm volatile(
        "mma.sync.aligned.m16n8k16.row.col.f32.f16.f16.f32 "
        "{%0,%1,%2,%3}, {%4,%5,%6,%7}, {%8,%9}, {%0,%1,%2,%3};"
        : "+f"(c[0]), "+f"(c[1]), "+f"(c[2]), "+f"(c[3])
        : "r"(a[0]), "r"(a[1]), "r"(a[2]), "r"(a[3]), "r"(b0), "r"(b1));
}

__device__ __forceinline__ void ldsm4(uint32_t* r, uint32_t addr) {
    asm volatile("ldmatrix.sync.aligned.m8n8.x4.shared.b16 {%0,%1,%2,%3}, [%4];"
        : "=r"(r[0]), "=r"(r[1]), "=r"(r[2]), "=r"(r[3]) : "r"(addr));
}

#define CP16(dst, src) \
    asm volatile("cp.async.cg.shared.global [%0], [%1], 16;" :: "r"(dst), "l"(src))
#define CP_COMMIT() asm volatile("cp.async.commit_group;" ::: "memory")
#define CP_WAIT2()  asm volatile("cp.async.wait_group 2;" ::: "memory")

// ============ fp16 GEMM: C[M,N] = A[M,K] * B[N,K]^T, fp32 accumulate =========
// 128x128x64 CTA tile, 128 threads, 4 warps (2M x 2N), warp tile 64x64.
// 3-stage cp.async pipeline, issue-before-wait ordering:
//   barrier (stage (c+2)%3 free) -> issue c+2 -> commit -> wait_group 2
//   (chunk c resident; 3 groups in flight during the wait) -> barrier -> compute
// EPI==0: C = acc   EPI==1: C = silu(acc + bias[n])
// OUTF==0: __half   OUTF==1: float
#define ST_STRIDE 32768u
template<int EPI, int OUTF>
__global__ void __launch_bounds__(128, 2)
gemm_f16(const __half* __restrict__ A, const __half* __restrict__ B,
         const float* __restrict__ bias, void* __restrict__ Cv,
         int M, int N, int K)
{
    extern __shared__ char smem[];
    const uint32_t al = smem_to_u32(smem);

    const int tid = threadIdx.x;
    const int wid = tid >> 5, l = tid & 31;
    const int wm = wid >> 1, wn = wid & 1;

    const size_t row0 = (size_t)blockIdx.y * 128;
    const size_t col0 = (size_t)blockIdx.x * 128;

    // ---- cp.async invariants: thread -> (row = tid>>3 + 16i, 16B-group = tid&7)
    const int ldr = tid >> 3;        // 0..15
    const int ldkg = tid & 7;
    const uint32_t sg = (uint32_t)(ldkg ^ (ldr & 7)) << 4;
    const __half* gA = A + (row0 + ldr) * (size_t)K + ldkg * 8;
    const __half* gB = B + (col0 + ldr) * (size_t)K + ldkg * 8;
    const uint32_t sA0 = al + ldr * 128 + sg;
    const uint32_t sB0 = al + 16384 + ldr * 128 + sg;

    // ---- fragment address invariants
    const uint32_t lr = l & 7, g01 = (l >> 3) & 1, g2 = (uint32_t)l >> 4;
    uint32_t aRow[4], bRow[4];
#pragma unroll
    for (int mi = 0; mi < 4; mi++)
        aRow[mi] = al + (uint32_t)(wm * 64 + mi * 16 + g01 * 8 + lr) * 128;
#pragma unroll
    for (int p = 0; p < 4; p++)
        bRow[p] = al + 16384 + (uint32_t)(wn * 64 + p * 16 + g2 * 8 + lr) * 128;

    float acc[4][8][4];
#pragma unroll
    for (int mi = 0; mi < 4; mi++)
#pragma unroll
        for (int j = 0; j < 8; j++)
#pragma unroll
            for (int t = 0; t < 4; t++) acc[mi][j][t] = 0.f;

    const int NC = K >> 6;     // 64 halfs per chunk

    // ---- prologue: chunks 0,1 into stages 0,1 (one group each)
#pragma unroll
    for (int s = 0; s < 2; s++) {
        const __half* pa = gA + s * 64;
        const __half* pb = gB + s * 64;
        uint32_t da = sA0 + s * ST_STRIDE;
        uint32_t db = sB0 + s * ST_STRIDE;
#pragma unroll
        for (int i = 0; i < 8; i++) {
            CP16(da + i * 2048, pa + (size_t)i * 16 * K);
            CP16(db + i * 2048, pb + (size_t)i * 16 * K);
        }
        CP_COMMIT();
    }

    for (int c = 0; c < NC; ++c) {
        __syncthreads();                    // all warps done with chunk c-1 ->
                                            // stage (c+2)%3 safe to overwrite
        if (c + 2 < NC) {
            const int st = (c + 2) % 3;
            const __half* pa = gA + (size_t)(c + 2) * 64;
            const __half* pb = gB + (size_t)(c + 2) * 64;
            uint32_t da = sA0 + st * ST_STRIDE;
            uint32_t db = sB0 + st * ST_STRIDE;
#pragma unroll
            for (int i = 0; i < 8; i++) {
                CP16(da + i * 2048, pa + (size_t)i * 16 * K);
                CP16(db + i * 2048, pb + (size_t)i * 16 * K);
            }
        }
        CP_COMMIT();
        CP_WAIT2();                         // chunk c complete (per-thread)
        __syncthreads();                    // chunk c visible to all warps

        const uint32_t stOff = (uint32_t)(c % 3) * ST_STRIDE;
#pragma unroll
        for (int s = 0; s < 4; s++) {       // 4 k16-steps per 64-K chunk
            const uint32_t aOff = stOff + ((((uint32_t)(2 * s) + g2) ^ lr) << 4);
            const uint32_t bOff = stOff + ((((uint32_t)(2 * s) + g01) ^ lr) << 4);
            uint32_t af[4][4], bf[4][4];
#pragma unroll
            for (int mi = 0; mi < 4; mi++) ldsm4(af[mi], aRow[mi] + aOff);
#pragma unroll
            for (int p = 0; p < 4; p++)  ldsm4(bf[p], bRow[p] + bOff);
#pragma unroll
            for (int mi = 0; mi < 4; mi++)
#pragma unroll
                for (int p = 0; p < 4; p++) {
                    mma_f16(acc[mi][2 * p],     af[mi], bf[p][0], bf[p][1]);
                    mma_f16(acc[mi][2 * p + 1], af[mi], bf[p][2], bf[p][3]);
                }
        }
    }

    // ---- epilogue
    const int gq = l >> 2, qq = l & 3;
#pragma unroll
    for (int mi = 0; mi < 4; mi++) {
        size_t r1 = row0 + wm * 64 + mi * 16 + gq;
#pragma unroll
        for (int nj = 0; nj < 8; nj++) {
            size_t cc = col0 + wn * 64 + nj * 8 + qq * 2;
            float v00 = acc[mi][nj][0], v01 = acc[mi][nj][1];
            float v10 = acc[mi][nj][2], v11 = acc[mi][nj][3];
            if (EPI == 1) {
                float2 bb = *(const float2*)(bias + cc);
                v00 = silu_f(v00 + bb.x); v01 = silu_f(v01 + bb.y);
                v10 = silu_f(v10 + bb.x); v11 = silu_f(v11 + bb.y);
            }
            if (OUTF == 1) {
                float* C = (float*)Cv;
                *(float2*)(C + r1 * N + cc)       = make_float2(v00, v01);
                *(float2*)(C + (r1 + 8) * N + cc) = make_float2(v10, v11);
            } else {
                __half* C = (__half*)Cv;
                *(__half2*)(C + r1 * N + cc)       = __floats2half2_rn(v00, v01);
                *(__half2*)(C + (r1 + 8) * N + cc) = __floats2half2_rn(v10, v11);
            }
        }
    }
}

// ---------------- fp32 -> fp16 convert (4 elems / thread) ---------------------
__global__ void to_half(const float* __restrict__ src, __half* __restrict__ dst,
                        long long n4)
{
    long long i = (long long)blockIdx.x * blockDim.x + threadIdx.x;
    if (i < n4) {
        float4 v = ((const float4*)src)[i];
        __half2* d2 = (__half2*)dst;
        d2[2 * i]     = __floats2half2_rn(v.x, v.y);
        d2[2 * i + 1] = __floats2half2_rn(v.z, v.w);
    }
}

// ------- fused depthwise causal (fwd) + anti-causal (bwd) conv, half2 ---------
__global__ void conv_dw(const __half* __restrict__ xz,
                        const float* __restrict__ wf, const float* __restrict__ bf,
                        const float* __restrict__ wb, const float* __restrict__ bb,
                        __half* __restrict__ cf, __half* __restrict__ cb)
{
    long long id = (long long)blockIdx.x * blockDim.x + threadIdx.x;  // half2 idx
    int c2 = (int)(id & (DIE / 2 - 1));       // half2 channel
    int c  = c2 * 2;
    long long m = id >> 9;                    // DIE/2 = 512 half2 per row
    int t = (int)(m & (TD - 1));
    const __half2* xz2 = (const __half2*)xz;
    long long base2 = m * DIE + c2;           // row stride = DIE half2s

    float af0 = bf[c],     af1 = bf[c + 1];
    float ab0 = bb[c],     ab1 = bb[c + 1];
#pragma unroll
    for (int k = 0; k < 7; k++) {
        float w0 = wf[c * 7 + k], w1 = wf[(c + 1) * 7 + k];
        float2 v = make_float2(0.f, 0.f);
        if (t - 6 + k >= 0) v = __half22float2(xz2[base2 + (long long)(k - 6) * DIE]);
        af0 = fmaf(v.x, w0, af0);
        af1 = fmaf(v.y, w1, af1);
    }
#pragma unroll
    for (int j = 0; j < 7; j++) {
        float w0 = wb[c * 7 + (6 - j)], w1 = wb[(c + 1) * 7 + (6 - j)];
        float2 v = make_float2(0.f, 0.f);
        if (t + 1 + j < TD) v = __half22float2(xz2[base2 + (long long)(j + 1) * DIE]);
        ab0 = fmaf(v.x, w0, ab0);
        ab1 = fmaf(v.y, w1, ab1);
    }
    ((__half2*)cf)[id] = __floats2half2_rn(af0, af1);
    ((__half2*)cb)[id] = __floats2half2_rn(ab0, ab1);
}

// ---------------- combine: shifts + diag + gate, half2 ------------------------
__global__ void combine_k(const __half* __restrict__ xz,
                          const __half* __restrict__ pf, const __half* __restrict__ pb,
                          const float* __restrict__ diag, const float* __restrict__ gate,
                          __half* __restrict__ y)
{
    long long id = (long long)blockIdx.x * blockDim.x + threadIdx.x;  // half2 idx
    int e2 = (int)(id & (DIE / 2 - 1));
    long long m = id >> 9;
    int t = (int)(m & (TD - 1));

    const __half2* pf2 = (const __half2*)pf;
    const __half2* pb2 = (const __half2*)pb;
    const __half2* xz2 = (const __half2*)xz;

    float2 yf = make_float2(0.f, 0.f);
    if (t > 0) yf = __half22float2(pf2[id - DIE / 2]);
    float2 yb = make_float2(0.f, 0.f);
    if (t < TD - 1) yb = __half22float2(pb2[id]);
    float2 xp = __half22float2(xz2[m * DIE + e2]);
    float2 z  = __half22float2(xz2[m * DIE + DIE / 2 + e2]);
    float2 dg = ((const float2*)diag)[e2];
    float gt = gate[0];
    float y0 = (yf.x + yb.x + xp.x * dg.x) * silu_f(z.x) * gt;
    float y1 = (yf.y + yb.y + xp.y * dg.y) * silu_f(z.y) * gt;
    ((__half2*)y)[id] = __floats2half2_rn(y0, y1);
}

// ---------------- residual + LayerNorm(512), o in fp16 ------------------------
__device__ __forceinline__ float warp_sum(float v) {
#pragma unroll
    for (int o = 16; o > 0; o >>= 1) v += __shfl_down_sync(0xffffffffu, v, o);
    return v;
}

__global__ void ln_kernel(const float* __restrict__ x, const __half* __restrict__ o,
                          const float* __restrict__ g, const float* __restrict__ b,
                          float* __restrict__ out)
{
    const int m = blockIdx.x;
    const int tid = threadIdx.x;
    const size_t base = (size_t)m * DD;

    float4 xv = ((const float4*)(x + base))[tid];
    const __half2* o2 = (const __half2*)(o + base);
    float2 oa = __half22float2(o2[tid * 2]);
    float2 ob = __half22float2(o2[tid * 2 + 1]);
    float4 h = make_float4(xv.x + oa.x, xv.y + oa.y, xv.z + ob.x, xv.w + ob.y);

    float s  = h.x + h.y + h.z + h.w;
    float ss = h.x * h.x + h.y * h.y + h.z * h.z + h.w * h.w;

    __shared__ float sh[4], sh2[4];
    float ws  = warp_sum(s);
    float wss = warp_sum(ss);
    if ((tid & 31) == 0) { sh[tid >> 5] = ws; sh2[tid >> 5] = wss; }
    __syncthreads();
    if (tid < 32) {
        float a  = (tid < 4) ? sh[tid]  : 0.f;
        float a2 = (tid < 4) ? sh2[tid] : 0.f;
        a  = warp_sum(a);
        a2 = warp_sum(a2);
        if (tid == 0) { sh[0] = a; sh2[0] = a2; }
    }
    __syncthreads();

    float mu  = sh[0] * (1.f / DD);
    float var = sh2[0] * (1.f / DD) - mu * mu;
    float inv = rsqrtf(var + LN_EPS);

    float4 gv = ((const float4*)g)[tid];
    float4 bv = ((const float4*)b)[tid];
    float4 r;
    r.x = (h.x - mu) * inv * gv.x + bv.x;
    r.y = (h.y - mu) * inv * gv.y + bv.y;
    r.z = (h.z - mu) * inv * gv.z + bv.z;
    r.w = (h.w - mu) * inv * gv.w + bv.w;
    ((float4*)(out + base))[tid] = r;
}

// ---------------- launch ------------------------------------------------------
#define GEMM_SMEM (3 * 32768)   // 96 KB -> 2 CTAs/SM

extern "C" void kernel_launch(void* const* d_in, const int* in_sizes, int n_in,
                              void* d_out, int out_size)
{
    const float* x          = (const float*)d_in[0];
    const float* in_proj_w  = (const float*)d_in[1];
    const float* conv_fwd_w = (const float*)d_in[2];
    const float* conv_fwd_b = (const float*)d_in[3];
    const float* proj_fwd_w = (const float*)d_in[4];
    const float* proj_fwd_b = (const float*)d_in[5];
    const float* conv_bwd_w = (const float*)d_in[6];
    const float* conv_bwd_b = (const float*)d_in[7];
    const float* proj_bwd_w = (const float*)d_in[8];
    const float* proj_bwd_b = (const float*)d_in[9];
    const float* diag       = (const float*)d_in[10];
    const float* gate       = (const float*)d_in[11];
    const float* out_proj_w = (const float*)d_in[12];
    const float* ln_g       = (const float*)d_in[13];
    const float* ln_b       = (const float*)d_in[14];

    __half *xzh, *cfh, *cbh, *pfh, *pbh, *yh, *oh, *xh, *w1h, *wfh, *wbh, *woh;
    cudaGetSymbolAddress((void**)&xzh, g_xzh);
    cudaGetSymbolAddress((void**)&cfh, g_cfh);
    cudaGetSymbolAddress((void**)&cbh, g_cbh);
    cudaGetSymbolAddress((void**)&pfh, g_pfh);
    cudaGetSymbolAddress((void**)&pbh, g_pbh);
    cudaGetSymbolAddress((void**)&yh,  g_yh);
    cudaGetSymbolAddress((void**)&oh,  g_oh);
    cudaGetSymbolAddress((void**)&xh,  g_xh);
    cudaGetSymbolAddress((void**)&w1h, g_w1h);
    cudaGetSymbolAddress((void**)&wfh, g_wfh);
    cudaGetSymbolAddress((void**)&wbh, g_wbh);
    cudaGetSymbolAddress((void**)&woh, g_woh);

    cudaFuncSetAttribute(gemm_f16<0, 0>, cudaFuncAttributeMaxDynamicSharedMemorySize, GEMM_SMEM);
    cudaFuncSetAttribute(gemm_f16<1, 0>, cudaFuncAttributeMaxDynamicSharedMemorySize, GEMM_SMEM);

    // 0) fp16 conversion of x + all weights
    {
        long long n4;
        n4 = (long long)NROWS * DD / 4;
        to_half<<<(unsigned)((n4 + 255) / 256), 256>>>(x, xh, n4);
        n4 = (long long)2 * DIE * DD / 4;
        to_half<<<(unsigned)((n4 + 255) / 256), 256>>>(in_proj_w, w1h, n4);
        n4 = (long long)DIE * DIE / 4;
        to_half<<<(unsigned)((n4 + 255) / 256), 256>>>(proj_fwd_w, wfh, n4);
        to_half<<<(unsigned)((n4 + 255) / 256), 256>>>(proj_bwd_w, wbh, n4);
        n4 = (long long)DD * DIE / 4;
        to_half<<<(unsigned)((n4 + 255) / 256), 256>>>(out_proj_w, woh, n4);
    }

    // 1) xz = x @ in_proj_w^T          (32768 x 2048, K=512)
    gemm_f16<0, 0><<<dim3(2048 / 128, NROWS / 128), 128, GEMM_SMEM>>>(
        xh, w1h, nullptr, xzh, NROWS, 2048, DD);
    // 2) both depthwise convs (half2)
    conv_dw<<<(NROWS * DIE / 2) / 256, 256>>>(xzh, conv_fwd_w, conv_fwd_b,
                                              conv_bwd_w, conv_bwd_b, cfh, cbh);
    // 3) pf = silu(cf @ wf^T + b)
    gemm_f16<1, 0><<<dim3(DIE / 128, NROWS / 128), 128, GEMM_SMEM>>>(
        cfh, wfh, proj_fwd_b, pfh, NROWS, DIE, DIE);
    // 4) pb = silu(cb @ wb^T + b)
    gemm_f16<1, 0><<<dim3(DIE / 128, NROWS / 128), 128, GEMM_SMEM>>>(
        cbh, wbh, proj_bwd_b, pbh, NROWS, DIE, DIE);
    // 5) y = (shift(pf) + mask(pb) + x_proj*diag) * silu(z) * gate (half2)
    combine_k<<<(NROWS * DIE / 2) / 256, 256>>>(xzh, pfh, pbh, diag, gate, yh);
    // 6) o = y @ wo^T             (32768 x 512, K=1024), fp16 out
    gemm_f16<0, 0><<<dim3(DD / 128, NROWS / 128), 128, GEMM_SMEM>>>(
        yh, woh, nullptr, oh, NROWS, DD, DIE);
    // 7) out = LayerNorm(x + o)
    ln_kernel<<<NROWS, 128>>>(x, oh, ln_g, ln_b, (float*)d_out);
}

// round 13
// speedup vs baseline: 1.0113x; 1.0113x over previous
#include <cuda_runtime.h>
#include <cuda_fp16.h>
#include <cstdint>

// Problem constants
#define BD    8
#define TD    4096
#define DD    512
#define DIE   1024          // DI
#define NROWS (BD*TD)       // 32768
#define LN_EPS 1e-5f

// ---------------- scratch (no cudaMalloc allowed) ----------------
__device__ __half g_xzh[(size_t)NROWS * 2 * DIE];   // gemm1 out (fp16)
__device__ __half g_cfh[(size_t)NROWS * DIE];
__device__ __half g_cbh[(size_t)NROWS * DIE];
__device__ __half g_pfh[(size_t)NROWS * DIE];
__device__ __half g_pbh[(size_t)NROWS * DIE];
__device__ __half g_yh [(size_t)NROWS * DIE];
__device__ __half g_oh [(size_t)NROWS * DD];        // out_proj result (fp16)
__device__ __half g_xh [(size_t)NROWS * DD];        // fp16 x
__device__ __half g_w1h[(size_t)2 * DIE * DD];
__device__ __half g_wfh[(size_t)DIE * DIE];
__device__ __half g_wbh[(size_t)DIE * DIE];
__device__ __half g_woh[(size_t)DD * DIE];

__device__ __forceinline__ float silu_f(float v) {
    return v / (1.f + __expf(-v));
}

__device__ __forceinline__ uint32_t smem_to_u32(const void* p) {
    uint32_t a;
    asm("{ .reg .u64 t; cvta.to.shared.u64 t, %1; cvt.u32.u64 %0, t; }" : "=r"(a) : "l"(p));
    return a;
}

__device__ __forceinline__ void mma_f16(float* c, const uint32_t* a,
                                        uint32_t b0, uint32_t b1) {
    asm volatile(
        "mma.sync.aligned.m16n8k16.row.col.f32.f16.f16.f32 "
        "{%0,%1,%2,%3}, {%4,%5,%6,%7}, {%8,%9}, {%0,%1,%2,%3};"
        : "+f"(c[0]), "+f"(c[1]), "+f"(c[2]), "+f"(c[3])
        : "r"(a[0]), "r"(a[1]), "r"(a[2]), "r"(a[3]), "r"(b0), "r"(b1));
}

__device__ __forceinline__ void ldsm4(uint32_t* r, uint32_t addr) {
    asm volatile("ldmatrix.sync.aligned.m8n8.x4.shared.b16 {%0,%1,%2,%3}, [%4];"
        : "=r"(r[0]), "=r"(r[1]), "=r"(r[2]), "=r"(r[3]) : "r"(addr));
}

#define CP16(dst, src) \
    asm volatile("cp.async.cg.shared.global [%0], [%1], 16;" :: "r"(dst), "l"(src))
#define CP_COMMIT() asm volatile("cp.async.commit_group;" ::: "memory")
#define CP_WAIT1()  asm volatile("cp.async.wait_group 1;" ::: "memory")

// ============ fp16 GEMM: C[M,N] = A[M,K] * B[N,K]^T, fp32 accumulate =========
// 128x128x64 CTA tile, 128 threads, 4 warps (2M x 2N), warp tile 64x64.
// 3-stage cp.async pipeline (stage = A 16KB + B 16KB), 2 CTAs/SM.
// R11-verified loop ordering: wait_group 1 -> barrier -> issue c+2 -> compute.
// EPI==0: C = acc   EPI==1: C = silu(acc + bias[n])
// OUTF==0: __half   OUTF==1: float
#define ST_STRIDE 32768u
template<int EPI, int OUTF>
__global__ void __launch_bounds__(128, 2)
gemm_f16(const __half* __restrict__ A, const __half* __restrict__ B,
         const float* __restrict__ bias, void* __restrict__ Cv,
         int M, int N, int K)
{
    extern __shared__ char smem[];
    const uint32_t al = smem_to_u32(smem);

    const int tid = threadIdx.x;
    const int wid = tid >> 5, l = tid & 31;
    const int wm = wid >> 1, wn = wid & 1;

    const size_t row0 = (size_t)blockIdx.y * 128;
    const size_t col0 = (size_t)blockIdx.x * 128;

    // ---- cp.async invariants: thread -> (row = tid>>3 + 16i, 16B-group = tid&7)
    const int ldr = tid >> 3;        // 0..15
    const int ldkg = tid & 7;
    const uint32_t sg = (uint32_t)(ldkg ^ (ldr & 7)) << 4;
    const __half* gA = A + (row0 + ldr) * (size_t)K + ldkg * 8;
    const __half* gB = B + (col0 + ldr) * (size_t)K + ldkg * 8;
    const uint32_t sA0 = al + ldr * 128 + sg;
    const uint32_t sB0 = al + 16384 + ldr * 128 + sg;

    // ---- fragment address invariants
    const uint32_t lr = l & 7, g01 = (l >> 3) & 1, g2 = (uint32_t)l >> 4;
    uint32_t aRow[4], bRow[4];
#pragma unroll
    for (int mi = 0; mi < 4; mi++)
        aRow[mi] = al + (uint32_t)(wm * 64 + mi * 16 + g01 * 8 + lr) * 128;
#pragma unroll
    for (int p = 0; p < 4; p++)
        bRow[p] = al + 16384 + (uint32_t)(wn * 64 + p * 16 + g2 * 8 + lr) * 128;

    float acc[4][8][4];
#pragma unroll
    for (int mi = 0; mi < 4; mi++)
#pragma unroll
        for (int j = 0; j < 8; j++)
#pragma unroll
            for (int t = 0; t < 4; t++) acc[mi][j][t] = 0.f;

    const int NC = K >> 6;     // 64 halfs per chunk

    // ---- prologue: chunks 0,1 into stages 0,1
#pragma unroll
    for (int s = 0; s < 2; s++) {
        const __half* pa = gA + s * 64;
        const __half* pb = gB + s * 64;
        uint32_t da = sA0 + s * ST_STRIDE;
        uint32_t db = sB0 + s * ST_STRIDE;
#pragma unroll
        for (int i = 0; i < 8; i++) {
            CP16(da + i * 2048, pa + (size_t)i * 16 * K);
            CP16(db + i * 2048, pb + (size_t)i * 16 * K);
        }
        CP_COMMIT();
    }

    for (int c = 0; c < NC; ++c) {
        CP_WAIT1();
        __syncthreads();
        if (c + 2 < NC) {
            const int st = (c + 2) % 3;
            const __half* pa = gA + (size_t)(c + 2) * 64;
            const __half* pb = gB + (size_t)(c + 2) * 64;
            uint32_t da = sA0 + st * ST_STRIDE;
            uint32_t db = sB0 + st * ST_STRIDE;
#pragma unroll
            for (int i = 0; i < 8; i++) {
                CP16(da + i * 2048, pa + (size_t)i * 16 * K);
                CP16(db + i * 2048, pb + (size_t)i * 16 * K);
            }
        }
        CP_COMMIT();

        const uint32_t stOff = (uint32_t)(c % 3) * ST_STRIDE;
#pragma unroll
        for (int s = 0; s < 4; s++) {          // 4 k16-steps per 64-K chunk
            const uint32_t aOff = stOff + ((((uint32_t)(2 * s) + g2) ^ lr) << 4);
            const uint32_t bOff = stOff + ((((uint32_t)(2 * s) + g01) ^ lr) << 4);
            uint32_t af[4][4], bf[4][4];
#pragma unroll
            for (int mi = 0; mi < 4; mi++) ldsm4(af[mi], aRow[mi] + aOff);
#pragma unroll
            for (int p = 0; p < 4; p++)  ldsm4(bf[p], bRow[p] + bOff);
#pragma unroll
            for (int mi = 0; mi < 4; mi++)
#pragma unroll
                for (int p = 0; p < 4; p++) {
                    mma_f16(acc[mi][2 * p],     af[mi], bf[p][0], bf[p][1]);
                    mma_f16(acc[mi][2 * p + 1], af[mi], bf[p][2], bf[p][3]);
                }
        }
    }

    // ---- epilogue
    const int gq = l >> 2, qq = l & 3;
#pragma unroll
    for (int mi = 0; mi < 4; mi++) {
        size_t r1 = row0 + wm * 64 + mi * 16 + gq;
#pragma unroll
        for (int nj = 0; nj < 8; nj++) {
            size_t cc = col0 + wn * 64 + nj * 8 + qq * 2;
            float v00 = acc[mi][nj][0], v01 = acc[mi][nj][1];
            float v10 = acc[mi][nj][2], v11 = acc[mi][nj][3];
            if (EPI == 1) {
                float2 bb = *(const float2*)(bias + cc);
                v00 = silu_f(v00 + bb.x); v01 = silu_f(v01 + bb.y);
                v10 = silu_f(v10 + bb.x); v11 = silu_f(v11 + bb.y);
            }
            if (OUTF == 1) {
                float* C = (float*)Cv;
                *(float2*)(C + r1 * N + cc)       = make_float2(v00, v01);
                *(float2*)(C + (r1 + 8) * N + cc) = make_float2(v10, v11);
            } else {
                __half* C = (__half*)Cv;
                *(__half2*)(C + r1 * N + cc)       = __floats2half2_rn(v00, v01);
                *(__half2*)(C + (r1 + 8) * N + cc) = __floats2half2_rn(v10, v11);
            }
        }
    }
}

// ------- merged fp32 -> fp16 convert over 5 segments (one launch) -------------
// Segment boundaries in float4 units, cumulative.
__global__ void to_half_multi(const float* s0, __half* d0, long long n0,
                              const float* s1, __half* d1, long long n1,
                              const float* s2, __half* d2, long long n2,
                              const float* s3, __half* d3, long long n3,
                              const float* s4, __half* d4, long long n4)
{
    long long i = (long long)blockIdx.x * blockDim.x + threadIdx.x;
    const float* src; __half* dst; long long off = i;
    if (off < n0)      { src = s0; dst = d0; }
    else if ((off -= n0) < n1) { src = s1; dst = d1; }
    else if ((off -= n1) < n2) { src = s2; dst = d2; }
    else if ((off -= n2) < n3) { src = s3; dst = d3; }
    else if ((off -= n3) < n4) { src = s4; dst = d4; }
    else return;
    float4 v = ((const float4*)src)[off];
    __half2* d2p = (__half2*)dst;
    d2p[2 * off]     = __floats2half2_rn(v.x, v.y);
    d2p[2 * off + 1] = __floats2half2_rn(v.z, v.w);
}

// ------- fused depthwise causal (fwd) + anti-causal (bwd) conv, half2 ---------
__global__ void conv_dw(const __half* __restrict__ xz,
                        const float* __restrict__ wf, const float* __restrict__ bf,
                        const float* __restrict__ wb, const float* __restrict__ bb,
                        __half* __restrict__ cf, __half* __restrict__ cb)
{
    long long id = (long long)blockIdx.x * blockDim.x + threadIdx.x;  // half2 idx
    int c2 = (int)(id & (DIE / 2 - 1));       // half2 channel
    int c  = c2 * 2;
    long long m = id >> 9;                    // DIE/2 = 512 half2 per row
    int t = (int)(m & (TD - 1));
    const __half2* xz2 = (const __half2*)xz;
    long long base2 = m * DIE + c2;           // row stride = DIE half2s

    float af0 = bf[c],     af1 = bf[c + 1];
    float ab0 = bb[c],     ab1 = bb[c + 1];
#pragma unroll
    for (int k = 0; k < 7; k++) {
        float w0 = wf[c * 7 + k], w1 = wf[(c + 1) * 7 + k];
        float2 v = make_float2(0.f, 0.f);
        if (t - 6 + k >= 0) v = __half22float2(xz2[base2 + (long long)(k - 6) * DIE]);
        af0 = fmaf(v.x, w0, af0);
        af1 = fmaf(v.y, w1, af1);
    }
#pragma unroll
    for (int j = 0; j < 7; j++) {
        float w0 = wb[c * 7 + (6 - j)], w1 = wb[(c + 1) * 7 + (6 - j)];
        float2 v = make_float2(0.f, 0.f);
        if (t + 1 + j < TD) v = __half22float2(xz2[base2 + (long long)(j + 1) * DIE]);
        ab0 = fmaf(v.x, w0, ab0);
        ab1 = fmaf(v.y, w1, ab1);
    }
    ((__half2*)cf)[id] = __floats2half2_rn(af0, af1);
    ((__half2*)cb)[id] = __floats2half2_rn(ab0, ab1);
}

// ---------------- combine: shifts + diag + gate, half2 ------------------------
__global__ void combine_k(const __half* __restrict__ xz,
                          const __half* __restrict__ pf, const __half* __restrict__ pb,
                          const float* __restrict__ diag, const float* __restrict__ gate,
                          __half* __restrict__ y)
{
    long long id = (long long)blockIdx.x * blockDim.x + threadIdx.x;  // half2 idx
    int e2 = (int)(id & (DIE / 2 - 1));
    long long m = id >> 9;
    int t = (int)(m & (TD - 1));

    const __half2* pf2 = (const __half2*)pf;
    const __half2* pb2 = (const __half2*)pb;
    const __half2* xz2 = (const __half2*)xz;

    float2 yf = make_float2(0.f, 0.f);
    if (t > 0) yf = __half22float2(pf2[id - DIE / 2]);
    float2 yb = make_float2(0.f, 0.f);
    if (t < TD - 1) yb = __half22float2(pb2[id]);
    float2 xp = __half22float2(xz2[m * DIE + e2]);
    float2 z  = __half22float2(xz2[m * DIE + DIE / 2 + e2]);
    float2 dg = ((const float2*)diag)[e2];
    float gt = gate[0];
    float y0 = (yf.x + yb.x + xp.x * dg.x) * silu_f(z.x) * gt;
    float y1 = (yf.y + yb.y + xp.y * dg.y) * silu_f(z.y) * gt;
    ((__half2*)y)[id] = __floats2half2_rn(y0, y1);
}

// ---------------- residual + LayerNorm(512), o in fp16 ------------------------
__device__ __forceinline__ float warp_sum(float v) {
#pragma unroll
    for (int o = 16; o > 0; o >>= 1) v += __shfl_down_sync(0xffffffffu, v, o);
    return v;
}

__global__ void ln_kernel(const float* __restrict__ x, const __half* __restrict__ o,
                          const float* __restrict__ g, const float* __restrict__ b,
                          float* __restrict__ out)
{
    const int m = blockIdx.x;
    const int tid = threadIdx.x;
    const size_t base = (size_t)m * DD;

    float4 xv = ((const float4*)(x + base))[tid];
    const __half2* o2 = (const __half2*)(o + base);
    float2 oa = __half22float2(o2[tid * 2]);
    float2 ob = __half22float2(o2[tid * 2 + 1]);
    float4 h = make_float4(xv.x + oa.x, xv.y + oa.y, xv.z + ob.x, xv.w + ob.y);

    float s  = h.x + h.y + h.z + h.w;
    float ss = h.x * h.x + h.y * h.y + h.z * h.z + h.w * h.w;

    __shared__ float sh[4], sh2[4];
    float ws  = warp_sum(s);
    float wss = warp_sum(ss);
    if ((tid & 31) == 0) { sh[tid >> 5] = ws; sh2[tid >> 5] = wss; }
    __syncthreads();
    if (tid < 32) {
        float a  = (tid < 4) ? sh[tid]  : 0.f;
        float a2 = (tid < 4) ? sh2[tid] : 0.f;
        a  = warp_sum(a);
        a2 = warp_sum(a2);
        if (tid == 0) { sh[0] = a; sh2[0] = a2; }
    }
    __syncthreads();

    float mu  = sh[0] * (1.f / DD);
    float var = sh2[0] * (1.f / DD) - mu * mu;
    float inv = rsqrtf(var + LN_EPS);

    float4 gv = ((const float4*)g)[tid];
    float4 bv = ((const float4*)b)[tid];
    float4 r;
    r.x = (h.x - mu) * inv * gv.x + bv.x;
    r.y = (h.y - mu) * inv * gv.y + bv.y;
    r.z = (h.z - mu) * inv * gv.z + bv.z;
    r.w = (h.w - mu) * inv * gv.w + bv.w;
    ((float4*)(out + base))[tid] = r;
}

// ---------------- launch ------------------------------------------------------
#define GEMM_SMEM (3 * 32768)   // 96 KB -> 2 CTAs/SM

extern "C" void kernel_launch(void* const* d_in, const int* in_sizes, int n_in,
                              void* d_out, int out_size)
{
    const float* x          = (const float*)d_in[0];
    const float* in_proj_w  = (const float*)d_in[1];
    const float* conv_fwd_w = (const float*)d_in[2];
    const float* conv_fwd_b = (const float*)d_in[3];
    const float* proj_fwd_w = (const float*)d_in[4];
    const float* proj_fwd_b = (const float*)d_in[5];
    const float* conv_bwd_w = (const float*)d_in[6];
    const float* conv_bwd_b = (const float*)d_in[7];
    const float* proj_bwd_w = (const float*)d_in[8];
    const float* proj_bwd_b = (const float*)d_in[9];
    const float* diag       = (const float*)d_in[10];
    const float* gate       = (const float*)d_in[11];
    const float* out_proj_w = (const float*)d_in[12];
    const float* ln_g       = (const float*)d_in[13];
    const float* ln_b       = (const float*)d_in[14];

    __half *xzh, *cfh, *cbh, *pfh, *pbh, *yh, *oh, *xh, *w1h, *wfh, *wbh, *woh;
    cudaGetSymbolAddress((void**)&xzh, g_xzh);
    cudaGetSymbolAddress((void**)&cfh, g_cfh);
    cudaGetSymbolAddress((void**)&cbh, g_cbh);
    cudaGetSymbolAddress((void**)&pfh, g_pfh);
    cudaGetSymbolAddress((void**)&pbh, g_pbh);
    cudaGetSymbolAddress((void**)&yh,  g_yh);
    cudaGetSymbolAddress((void**)&oh,  g_oh);
    cudaGetSymbolAddress((void**)&xh,  g_xh);
    cudaGetSymbolAddress((void**)&w1h, g_w1h);
    cudaGetSymbolAddress((void**)&wfh, g_wfh);
    cudaGetSymbolAddress((void**)&wbh, g_wbh);
    cudaGetSymbolAddress((void**)&woh, g_woh);

    cudaFuncSetAttribute(gemm_f16<0, 0>, cudaFuncAttributeMaxDynamicSharedMemorySize, GEMM_SMEM);
    cudaFuncSetAttribute(gemm_f16<1, 0>, cudaFuncAttributeMaxDynamicSharedMemorySize, GEMM_SMEM);

    // 0) fp16 conversion of x + all weights (single launch)
    {
        const long long n0 = (long long)NROWS * DD / 4;       // x
        const long long n1 = (long long)2 * DIE * DD / 4;     // in_proj_w
        const long long n2 = (long long)DIE * DIE / 4;        // proj_fwd_w
        const long long n3 = (long long)DIE * DIE / 4;        // proj_bwd_w
        const long long n4 = (long long)DD * DIE / 4;         // out_proj_w
        const long long nt = n0 + n1 + n2 + n3 + n4;
        to_half_multi<<<(unsigned)((nt + 255) / 256), 256>>>(
            x, xh, n0, in_proj_w, w1h, n1, proj_fwd_w, wfh, n2,
            proj_bwd_w, wbh, n3, out_proj_w, woh, n4);
    }

    // 1) xz = x @ in_proj_w^T          (32768 x 2048, K=512)
    gemm_f16<0, 0><<<dim3(2048 / 128, NROWS / 128), 128, GEMM_SMEM>>>(
        xh, w1h, nullptr, xzh, NROWS, 2048, DD);
    // 2) both depthwise convs (half2)
    conv_dw<<<(NROWS * DIE / 2) / 256, 256>>>(xzh, conv_fwd_w, conv_fwd_b,
                                              conv_bwd_w, conv_bwd_b, cfh, cbh);
    // 3) pf = silu(cf @ wf^T + b)
    gemm_f16<1, 0><<<dim3(DIE / 128, NROWS / 128), 128, GEMM_SMEM>>>(
        cfh, wfh, proj_fwd_b, pfh, NROWS, DIE, DIE);
    // 4) pb = silu(cb @ wb^T + b)
    gemm_f16<1, 0><<<dim3(DIE / 128, NROWS / 128), 128, GEMM_SMEM>>>(
        cbh, wbh, proj_bwd_b, pbh, NROWS, DIE, DIE);
    // 5) y = (shift(pf) + mask(pb) + x_proj*diag) * silu(z) * gate (half2)
    combine_k<<<(NROWS * DIE / 2) / 256, 256>>>(xzh, pfh, pbh, diag, gate, yh);
    // 6) o = y @ wo^T             (32768 x 512, K=1024), fp16 out
    gemm_f16<0, 0><<<dim3(DD / 128, NROWS / 128), 128, GEMM_SMEM>>>(
        yh, woh, nullptr, oh, NROWS, DD, DIE);
    // 7) out = LayerNorm(x + o)
    ln_kernel<<<NROWS, 128>>>(x, oh, ln_g, ln_b, (float*)d_out);
}

// round 14
// speedup vs baseline: 1.2437x; 1.2298x over previous
#include <cuda_runtime.h>
#include <cuda_fp16.h>
#include <cstdint>

// Problem constants
#define BD    8
#define TD    4096
#define DD    512
#define DIE   1024          // DI
#define NROWS (BD*TD)       // 32768
#define LN_EPS 1e-5f

// ---------------- scratch (no cudaMalloc allowed) ----------------
__device__ __half g_xzh[(size_t)NROWS * 2 * DIE];   // gemm1 out (fp16)
__device__ __half g_cfh[(size_t)NROWS * DIE];
__device__ __half g_cbh[(size_t)NROWS * DIE];
__device__ __half g_pfh[(size_t)NROWS * DIE];
__device__ __half g_pbh[(size_t)NROWS * DIE];
__device__ __half g_yh [(size_t)NROWS * DIE];
__device__ __half g_oh [(size_t)NROWS * DD];        // out_proj result (fp16)
__device__ __half g_xh [(size_t)NROWS * DD];        // fp16 x
__device__ __half g_w1h[(size_t)2 * DIE * DD];
__device__ __half g_wfh[(size_t)DIE * DIE];
__device__ __half g_wbh[(size_t)DIE * DIE];
__device__ __half g_woh[(size_t)DD * DIE];

__device__ __forceinline__ float silu_f(float v) {
    return v / (1.f + __expf(-v));
}

__device__ __forceinline__ uint32_t smem_to_u32(const void* p) {
    uint32_t a;
    asm("{ .reg .u64 t; cvta.to.shared.u64 t, %1; cvt.u32.u64 %0, t; }" : "=r"(a) : "l"(p));
    return a;
}

__device__ __forceinline__ void mma_f16(float* c, const uint32_t* a,
                                        uint32_t b0, uint32_t b1) {
    asm volatile(
        "mma.sync.aligned.m16n8k16.row.col.f32.f16.f16.f32 "
        "{%0,%1,%2,%3}, {%4,%5,%6,%7}, {%8,%9}, {%0,%1,%2,%3};"
        : "+f"(c[0]), "+f"(c[1]), "+f"(c[2]), "+f"(c[3])
        : "r"(a[0]), "r"(a[1]), "r"(a[2]), "r"(a[3]), "r"(b0), "r"(b1));
}

__device__ __forceinline__ void ldsm4(uint32_t* r, uint32_t addr) {
    asm volatile("ldmatrix.sync.aligned.m8n8.x4.shared.b16 {%0,%1,%2,%3}, [%4];"
        : "=r"(r[0]), "=r"(r[1]), "=r"(r[2]), "=r"(r[3]) : "r"(addr));
}

#define CP16(dst, src) \
    asm volatile("cp.async.cg.shared.global [%0], [%1], 16;" :: "r"(dst), "l"(src))
#define CP_COMMIT() asm volatile("cp.async.commit_group;" ::: "memory")
#define CP_WAIT1()  asm volatile("cp.async.wait_group 1;" ::: "memory")

// ============ fp16 GEMM: C[M,N] = A[M,K] * B[N,K]^T, fp32 accumulate =========
// 128x128x64 CTA tile, 128 threads, 4 warps (2M x 2N), warp tile 64x64.
// 3-stage cp.async pipeline (stage = A 16KB + B 16KB), 2 CTAs/SM.
// R11-verified loop ordering: wait_group 1 -> barrier -> issue c+2 -> compute.
// EPI==0: C = acc   EPI==1: C = silu(acc + bias[n])
// OUTF==0: __half   OUTF==1: float
#define ST_STRIDE 32768u
template<int EPI, int OUTF>
__global__ void __launch_bounds__(128, 2)
gemm_f16(const __half* __restrict__ A, const __half* __restrict__ B,
         const float* __restrict__ bias, void* __restrict__ Cv,
         int M, int N, int K)
{
    extern __shared__ char smem[];
    const uint32_t al = smem_to_u32(smem);

    const int tid = threadIdx.x;
    const int wid = tid >> 5, l = tid & 31;
    const int wm = wid >> 1, wn = wid & 1;

    const size_t row0 = (size_t)blockIdx.y * 128;
    const size_t col0 = (size_t)blockIdx.x * 128;

    // ---- cp.async invariants: thread -> (row = tid>>3 + 16i, 16B-group = tid&7)
    const int ldr = tid >> 3;        // 0..15
    const int ldkg = tid & 7;
    const uint32_t sg = (uint32_t)(ldkg ^ (ldr & 7)) << 4;
    const __half* gA = A + (row0 + ldr) * (size_t)K + ldkg * 8;
    const __half* gB = B + (col0 + ldr) * (size_t)K + ldkg * 8;
    const uint32_t sA0 = al + ldr * 128 + sg;
    const uint32_t sB0 = al + 16384 + ldr * 128 + sg;

    // ---- fragment address invariants
    const uint32_t lr = l & 7, g01 = (l >> 3) & 1, g2 = (uint32_t)l >> 4;
    uint32_t aRow[4], bRow[4];
#pragma unroll
    for (int mi = 0; mi < 4; mi++)
        aRow[mi] = al + (uint32_t)(wm * 64 + mi * 16 + g01 * 8 + lr) * 128;
#pragma unroll
    for (int p = 0; p < 4; p++)
        bRow[p] = al + 16384 + (uint32_t)(wn * 64 + p * 16 + g2 * 8 + lr) * 128;

    float acc[4][8][4];
#pragma unroll
    for (int mi = 0; mi < 4; mi++)
#pragma unroll
        for (int j = 0; j < 8; j++)
#pragma unroll
            for (int t = 0; t < 4; t++) acc[mi][j][t] = 0.f;

    const int NC = K >> 6;     // 64 halfs per chunk

    // ---- prologue: chunks 0,1 into stages 0,1
#pragma unroll
    for (int s = 0; s < 2; s++) {
        const __half* pa = gA + s * 64;
        const __half* pb = gB + s * 64;
        uint32_t da = sA0 + s * ST_STRIDE;
        uint32_t db = sB0 + s * ST_STRIDE;
#pragma unroll
        for (int i = 0; i < 8; i++) {
            CP16(da + i * 2048, pa + (size_t)i * 16 * K);
            CP16(db + i * 2048, pb + (size_t)i * 16 * K);
        }
        CP_COMMIT();
    }

    for (int c = 0; c < NC; ++c) {
        CP_WAIT1();
        __syncthreads();
        if (c + 2 < NC) {
            const int st = (c + 2) % 3;
            const __half* pa = gA + (size_t)(c + 2) * 64;
            const __half* pb = gB + (size_t)(c + 2) * 64;
            uint32_t da = sA0 + st * ST_STRIDE;
            uint32_t db = sB0 + st * ST_STRIDE;
#pragma unroll
            for (int i = 0; i < 8; i++) {
                CP16(da + i * 2048, pa + (size_t)i * 16 * K);
                CP16(db + i * 2048, pb + (size_t)i * 16 * K);
            }
        }
        CP_COMMIT();

        const uint32_t stOff = (uint32_t)(c % 3) * ST_STRIDE;
#pragma unroll
        for (int s = 0; s < 4; s++) {          // 4 k16-steps per 64-K chunk
            const uint32_t aOff = stOff + ((((uint32_t)(2 * s) + g2) ^ lr) << 4);
            const uint32_t bOff = stOff + ((((uint32_t)(2 * s) + g01) ^ lr) << 4);
            uint32_t af[4][4], bf[4][4];
#pragma unroll
            for (int mi = 0; mi < 4; mi++) ldsm4(af[mi], aRow[mi] + aOff);
#pragma unroll
            for (int p = 0; p < 4; p++)  ldsm4(bf[p], bRow[p] + bOff);
#pragma unroll
            for (int mi = 0; mi < 4; mi++)
#pragma unroll
                for (int p = 0; p < 4; p++) {
                    mma_f16(acc[mi][2 * p],     af[mi], bf[p][0], bf[p][1]);
                    mma_f16(acc[mi][2 * p + 1], af[mi], bf[p][2], bf[p][3]);
                }
        }
    }

    // ---- epilogue
    const int gq = l >> 2, qq = l & 3;
#pragma unroll
    for (int mi = 0; mi < 4; mi++) {
        size_t r1 = row0 + wm * 64 + mi * 16 + gq;
#pragma unroll
        for (int nj = 0; nj < 8; nj++) {
            size_t cc = col0 + wn * 64 + nj * 8 + qq * 2;
            float v00 = acc[mi][nj][0], v01 = acc[mi][nj][1];
            float v10 = acc[mi][nj][2], v11 = acc[mi][nj][3];
            if (EPI == 1) {
                float2 bb = *(const float2*)(bias + cc);
                v00 = silu_f(v00 + bb.x); v01 = silu_f(v01 + bb.y);
                v10 = silu_f(v10 + bb.x); v11 = silu_f(v11 + bb.y);
            }
            if (OUTF == 1) {
                float* C = (float*)Cv;
                *(float2*)(C + r1 * N + cc)       = make_float2(v00, v01);
                *(float2*)(C + (r1 + 8) * N + cc) = make_float2(v10, v11);
            } else {
                __half* C = (__half*)Cv;
                *(__half2*)(C + r1 * N + cc)       = __floats2half2_rn(v00, v01);
                *(__half2*)(C + (r1 + 8) * N + cc) = __floats2half2_rn(v10, v11);
            }
        }
    }
}

// ------- merged fp32 -> fp16 convert over 5 segments (one launch) -------------
__global__ void to_half_multi(const float* s0, __half* d0, long long n0,
                              const float* s1, __half* d1, long long n1,
                              const float* s2, __half* d2, long long n2,
                              const float* s3, __half* d3, long long n3,
                              const float* s4, __half* d4, long long n4)
{
    long long i = (long long)blockIdx.x * blockDim.x + threadIdx.x;
    const float* src; __half* dst; long long off = i;
    if (off < n0)      { src = s0; dst = d0; }
    else if ((off -= n0) < n1) { src = s1; dst = d1; }
    else if ((off -= n1) < n2) { src = s2; dst = d2; }
    else if ((off -= n2) < n3) { src = s3; dst = d3; }
    else if ((off -= n3) < n4) { src = s4; dst = d4; }
    else return;
    float4 v = ((const float4*)src)[off];
    __half2* d2p = (__half2*)dst;
    d2p[2 * off]     = __floats2half2_rn(v.x, v.y);
    d2p[2 * off + 1] = __floats2half2_rn(v.z, v.w);
}

// ------- depthwise causal (fwd) + anti-causal (bwd) conv, t-tiled -------------
// Each thread: one half2 channel (c2), TT=16 consecutive timesteps. Loads the
// 29-row window v[t0-6 .. t0+22] ONCE (vs 14 loads/output in the naive form),
// then computes all 16 fwd+bwd outputs. Tiles align to sequences (16 | 4096).
//   cf[t0+i] = bf + sum_k  wf[k]    * v[i+k]        (k=0..6)
//   cb[t0+i] = bb + sum_j2 wb[6-j2] * v[i+7+j2]     (j2=0..6)
#define CONV_TT 16
__global__ void conv_dw_tiled(const __half* __restrict__ xz,
                              const float* __restrict__ wf, const float* __restrict__ bf,
                              const float* __restrict__ wb, const float* __restrict__ bb,
                              __half* __restrict__ cf, __half* __restrict__ cb)
{
    const long long id = (long long)blockIdx.x * blockDim.x + threadIdx.x;
    const int c2 = (int)(id & (DIE / 2 - 1));       // half2 channel, warp-contig
    const int c  = c2 * 2;
    const long long tile = id >> 9;                  // DIE/2 = 512 c2 per tile-row
    const long long m0 = tile * CONV_TT;             // global row start
    const int t0 = (int)(m0 & (TD - 1));             // within-sequence start

    const __half2* xz2 = (const __half2*)xz;

    // window loads (rows m0-6+j, j = 0..TT+12), masked at sequence edges
    float2 v[CONV_TT + 13];
#pragma unroll
    for (int j = 0; j < CONV_TT + 13; j++) {
        int t = t0 - 6 + j;
        v[j] = make_float2(0.f, 0.f);
        if (t >= 0 && t < TD)
            v[j] = __half22float2(xz2[(m0 - 6 + j) * DIE + c2]);
    }

    // weights for this channel pair
    float wf0[7], wf1[7], wbr0[7], wbr1[7];
#pragma unroll
    for (int k = 0; k < 7; k++) {
        wf0[k]  = wf[c * 7 + k];
        wf1[k]  = wf[(c + 1) * 7 + k];
        wbr0[k] = wb[c * 7 + (6 - k)];       // flipped bwd weights
        wbr1[k] = wb[(c + 1) * 7 + (6 - k)];
    }
    const float bf0 = bf[c], bf1 = bf[c + 1];
    const float bb0 = bb[c], bb1 = bb[c + 1];

    __half2* cf2 = (__half2*)cf;
    __half2* cb2 = (__half2*)cb;
#pragma unroll
    for (int i = 0; i < CONV_TT; i++) {
        float af0 = bf0, af1 = bf1, ab0 = bb0, ab1 = bb1;
#pragma unroll
        for (int k = 0; k < 7; k++) {
            af0 = fmaf(v[i + k].x, wf0[k], af0);
            af1 = fmaf(v[i + k].y, wf1[k], af1);
            ab0 = fmaf(v[i + 7 + k].x, wbr0[k], ab0);
            ab1 = fmaf(v[i + 7 + k].y, wbr1[k], ab1);
        }
        const long long out = (m0 + i) * (DIE / 2) + c2;
        cf2[out] = __floats2half2_rn(af0, af1);
        cb2[out] = __floats2half2_rn(ab0, ab1);
    }
}

// ---------------- combine: shifts + diag + gate, half2 ------------------------
__global__ void combine_k(const __half* __restrict__ xz,
                          const __half* __restrict__ pf, const __half* __restrict__ pb,
                          const float* __restrict__ diag, const float* __restrict__ gate,
                          __half* __restrict__ y)
{
    long long id = (long long)blockIdx.x * blockDim.x + threadIdx.x;  // half2 idx
    int e2 = (int)(id & (DIE / 2 - 1));
    long long m = id >> 9;
    int t = (int)(m & (TD - 1));

    const __half2* pf2 = (const __half2*)pf;
    const __half2* pb2 = (const __half2*)pb;
    const __half2* xz2 = (const __half2*)xz;

    float2 yf = make_float2(0.f, 0.f);
    if (t > 0) yf = __half22float2(pf2[id - DIE / 2]);
    float2 yb = make_float2(0.f, 0.f);
    if (t < TD - 1) yb = __half22float2(pb2[id]);
    float2 xp = __half22float2(xz2[m * DIE + e2]);
    float2 z  = __half22float2(xz2[m * DIE + DIE / 2 + e2]);
    float2 dg = ((const float2*)diag)[e2];
    float gt = gate[0];
    float y0 = (yf.x + yb.x + xp.x * dg.x) * silu_f(z.x) * gt;
    float y1 = (yf.y + yb.y + xp.y * dg.y) * silu_f(z.y) * gt;
    ((__half2*)y)[id] = __floats2half2_rn(y0, y1);
}

// ---------------- residual + LayerNorm(512), o in fp16 ------------------------
__device__ __forceinline__ float warp_sum(float v) {
#pragma unroll
    for (int o = 16; o > 0; o >>= 1) v += __shfl_down_sync(0xffffffffu, v, o);
    return v;
}

__global__ void ln_kernel(const float* __restrict__ x, const __half* __restrict__ o,
                          const float* __restrict__ g, const float* __restrict__ b,
                          float* __restrict__ out)
{
    const int m = blockIdx.x;
    const int tid = threadIdx.x;
    const size_t base = (size_t)m * DD;

    float4 xv = ((const float4*)(x + base))[tid];
    const __half2* o2 = (const __half2*)(o + base);
    float2 oa = __half22float2(o2[tid * 2]);
    float2 ob = __half22float2(o2[tid * 2 + 1]);
    float4 h = make_float4(xv.x + oa.x, xv.y + oa.y, xv.z + ob.x, xv.w + ob.y);

    float s  = h.x + h.y + h.z + h.w;
    float ss = h.x * h.x + h.y * h.y + h.z * h.z + h.w * h.w;

    __shared__ float sh[4], sh2[4];
    float ws  = warp_sum(s);
    float wss = warp_sum(ss);
    if ((tid & 31) == 0) { sh[tid >> 5] = ws; sh2[tid >> 5] = wss; }
    __syncthreads();
    if (tid < 32) {
        float a  = (tid < 4) ? sh[tid]  : 0.f;
        float a2 = (tid < 4) ? sh2[tid] : 0.f;
        a  = warp_sum(a);
        a2 = warp_sum(a2);
        if (tid == 0) { sh[0] = a; sh2[0] = a2; }
    }
    __syncthreads();

    float mu  = sh[0] * (1.f / DD);
    float var = sh2[0] * (1.f / DD) - mu * mu;
    float inv = rsqrtf(var + LN_EPS);

    float4 gv = ((const float4*)g)[tid];
    float4 bv = ((const float4*)b)[tid];
    float4 r;
    r.x = (h.x - mu) * inv * gv.x + bv.x;
    r.y = (h.y - mu) * inv * gv.y + bv.y;
    r.z = (h.z - mu) * inv * gv.z + bv.z;
    r.w = (h.w - mu) * inv * gv.w + bv.w;
    ((float4*)(out + base))[tid] = r;
}

// ---------------- launch ------------------------------------------------------
#define GEMM_SMEM (3 * 32768)   // 96 KB -> 2 CTAs/SM

extern "C" void kernel_launch(void* const* d_in, const int* in_sizes, int n_in,
                              void* d_out, int out_size)
{
    const float* x          = (const float*)d_in[0];
    const float* in_proj_w  = (const float*)d_in[1];
    const float* conv_fwd_w = (const float*)d_in[2];
    const float* conv_fwd_b = (const float*)d_in[3];
    const float* proj_fwd_w = (const float*)d_in[4];
    const float* proj_fwd_b = (const float*)d_in[5];
    const float* conv_bwd_w = (const float*)d_in[6];
    const float* conv_bwd_b = (const float*)d_in[7];
    const float* proj_bwd_w = (const float*)d_in[8];
    const float* proj_bwd_b = (const float*)d_in[9];
    const float* diag       = (const float*)d_in[10];
    const float* gate       = (const float*)d_in[11];
    const float* out_proj_w = (const float*)d_in[12];
    const float* ln_g       = (const float*)d_in[13];
    const float* ln_b       = (const float*)d_in[14];

    __half *xzh, *cfh, *cbh, *pfh, *pbh, *yh, *oh, *xh, *w1h, *wfh, *wbh, *woh;
    cudaGetSymbolAddress((void**)&xzh, g_xzh);
    cudaGetSymbolAddress((void**)&cfh, g_cfh);
    cudaGetSymbolAddress((void**)&cbh, g_cbh);
    cudaGetSymbolAddress((void**)&pfh, g_pfh);
    cudaGetSymbolAddress((void**)&pbh, g_pbh);
    cudaGetSymbolAddress((void**)&yh,  g_yh);
    cudaGetSymbolAddress((void**)&oh,  g_oh);
    cudaGetSymbolAddress((void**)&xh,  g_xh);
    cudaGetSymbolAddress((void**)&w1h, g_w1h);
    cudaGetSymbolAddress((void**)&wfh, g_wfh);
    cudaGetSymbolAddress((void**)&wbh, g_wbh);
    cudaGetSymbolAddress((void**)&woh, g_woh);

    cudaFuncSetAttribute(gemm_f16<0, 0>, cudaFuncAttributeMaxDynamicSharedMemorySize, GEMM_SMEM);
    cudaFuncSetAttribute(gemm_f16<1, 0>, cudaFuncAttributeMaxDynamicSharedMemorySize, GEMM_SMEM);

    // 0) fp16 conversion of x + all weights (single launch)
    {
        const long long n0 = (long long)NROWS * DD / 4;       // x
        const long long n1 = (long long)2 * DIE * DD / 4;     // in_proj_w
        const long long n2 = (long long)DIE * DIE / 4;        // proj_fwd_w
        const long long n3 = (long long)DIE * DIE / 4;        // proj_bwd_w
        const long long n4 = (long long)DD * DIE / 4;         // out_proj_w
        const long long nt = n0 + n1 + n2 + n3 + n4;
        to_half_multi<<<(unsigned)((nt + 255) / 256), 256>>>(
            x, xh, n0, in_proj_w, w1h, n1, proj_fwd_w, wfh, n2,
            proj_bwd_w, wbh, n3, out_proj_w, woh, n4);
    }

    // 1) xz = x @ in_proj_w^T          (32768 x 2048, K=512)
    gemm_f16<0, 0><<<dim3(2048 / 128, NROWS / 128), 128, GEMM_SMEM>>>(
        xh, w1h, nullptr, xzh, NROWS, 2048, DD);
    // 2) both depthwise convs (t-tiled, window in registers)
    conv_dw_tiled<<<(unsigned)(((long long)(NROWS / CONV_TT) * (DIE / 2)) / 256), 256>>>(
        xzh, conv_fwd_w, conv_fwd_b, conv_bwd_w, conv_bwd_b, cfh, cbh);
    // 3) pf = silu(cf @ wf^T + b)
    gemm_f16<1, 0><<<dim3(DIE / 128, NROWS / 128), 128, GEMM_SMEM>>>(
        cfh, wfh, proj_fwd_b, pfh, NROWS, DIE, DIE);
    // 4) pb = silu(cb @ wb^T + b)
    gemm_f16<1, 0><<<dim3(DIE / 128, NROWS / 128), 128, GEMM_SMEM>>>(
        cbh, wbh, proj_bwd_b, pbh, NROWS, DIE, DIE);
    // 5) y = (shift(pf) + mask(pb) + x_proj*diag) * silu(z) * gate (half2)
    combine_k<<<(NROWS * DIE / 2) / 256, 256>>>(xzh, pfh, pbh, diag, gate, yh);
    // 6) o = y @ wo^T             (32768 x 512, K=1024), fp16 out
    gemm_f16<0, 0><<<dim3(DD / 128, NROWS / 128), 128, GEMM_SMEM>>>(
        yh, woh, nullptr, oh, NROWS, DD, DIE);
    // 7) out = LayerNorm(x + o)
    ln_kernel<<<NROWS, 128>>>(x, oh, ln_g, ln_b, (float*)d_out);
}

// round 15
// speedup vs baseline: 1.2686x; 1.0200x over previous
#include <cuda_runtime.h>
#include <cuda_fp16.h>
#include <cstdint>

// Problem constants
#define BD    8
#define TD    4096
#define DD    512
#define DIE   1024          // DI
#define NROWS (BD*TD)       // 32768
#define LN_EPS 1e-5f

// ---------------- scratch (no cudaMalloc allowed) ----------------
__device__ __half g_xzh[(size_t)NROWS * 2 * DIE];   // gemm1 out (fp16)
__device__ __half g_cfh[(size_t)NROWS * DIE];
__device__ __half g_cbh[(size_t)NROWS * DIE];
__device__ __half g_pfh[(size_t)NROWS * DIE];
__device__ __half g_pbh[(size_t)NROWS * DIE];
__device__ __half g_yh [(size_t)NROWS * DIE];
__device__ __half g_oh [(size_t)NROWS * DD];        // out_proj result (fp16)
__device__ __half g_xh [(size_t)NROWS * DD];        // fp16 x
__device__ __half g_w1h[(size_t)2 * DIE * DD];
__device__ __half g_wfh[(size_t)DIE * DIE];
__device__ __half g_wbh[(size_t)DIE * DIE];
__device__ __half g_woh[(size_t)DD * DIE];

__device__ __forceinline__ float silu_f(float v) {
    return v / (1.f + __expf(-v));
}

__device__ __forceinline__ uint32_t smem_to_u32(const void* p) {
    uint32_t a;
    asm("{ .reg .u64 t; cvta.to.shared.u64 t, %1; cvt.u32.u64 %0, t; }" : "=r"(a) : "l"(p));
    return a;
}

__device__ __forceinline__ void mma_f16(float* c, const uint32_t* a,
                                        uint32_t b0, uint32_t b1) {
    asm volatile(
        "mma.sync.aligned.m16n8k16.row.col.f32.f16.f16.f32 "
        "{%0,%1,%2,%3}, {%4,%5,%6,%7}, {%8,%9}, {%0,%1,%2,%3};"
        : "+f"(c[0]), "+f"(c[1]), "+f"(c[2]), "+f"(c[3])
        : "r"(a[0]), "r"(a[1]), "r"(a[2]), "r"(a[3]), "r"(b0), "r"(b1));
}

__device__ __forceinline__ void ldsm4(uint32_t* r, uint32_t addr) {
    asm volatile("ldmatrix.sync.aligned.m8n8.x4.shared.b16 {%0,%1,%2,%3}, [%4];"
        : "=r"(r[0]), "=r"(r[1]), "=r"(r[2]), "=r"(r[3]) : "r"(addr));
}

#define CP16(dst, src) \
    asm volatile("cp.async.cg.shared.global [%0], [%1], 16;" :: "r"(dst), "l"(src))
#define CP_COMMIT() asm volatile("cp.async.commit_group;" ::: "memory")
#define CP_WAIT1()  asm volatile("cp.async.wait_group 1;" ::: "memory")

// ====== fp16 GEMM core (device func): C[M,N] = A[M,K]*B[N,K]^T, fp32 acc =====
// 128x128x64 CTA tile, 128 threads, 4 warps (2M x 2N), warp tile 64x64.
// 3-stage cp.async pipeline (stage = A 16KB + B 16KB), 2 CTAs/SM.
// EPI==0: C = acc   EPI==1: C = silu(acc + bias[n])
// OUTF==0: __half   OUTF==1: float
#define ST_STRIDE 32768u
template<int EPI, int OUTF>
__device__ __forceinline__ void gemm_body(
        const __half* __restrict__ A, const __half* __restrict__ B,
        const float* __restrict__ bias, void* __restrict__ Cv,
        int M, int N, int K, char* smem)
{
    const uint32_t al = smem_to_u32(smem);

    const int tid = threadIdx.x;
    const int wid = tid >> 5, l = tid & 31;
    const int wm = wid >> 1, wn = wid & 1;

    const size_t row0 = (size_t)blockIdx.y * 128;
    const size_t col0 = (size_t)blockIdx.x * 128;

    // ---- cp.async invariants: thread -> (row = tid>>3 + 16i, 16B-group = tid&7)
    const int ldr = tid >> 3;        // 0..15
    const int ldkg = tid & 7;
    const uint32_t sg = (uint32_t)(ldkg ^ (ldr & 7)) << 4;
    const __half* gA = A + (row0 + ldr) * (size_t)K + ldkg * 8;
    const __half* gB = B + (col0 + ldr) * (size_t)K + ldkg * 8;
    const uint32_t sA0 = al + ldr * 128 + sg;
    const uint32_t sB0 = al + 16384 + ldr * 128 + sg;

    // ---- fragment address invariants
    const uint32_t lr = l & 7, g01 = (l >> 3) & 1, g2 = (uint32_t)l >> 4;
    uint32_t aRow[4], bRow[4];
#pragma unroll
    for (int mi = 0; mi < 4; mi++)
        aRow[mi] = al + (uint32_t)(wm * 64 + mi * 16 + g01 * 8 + lr) * 128;
#pragma unroll
    for (int p = 0; p < 4; p++)
        bRow[p] = al + 16384 + (uint32_t)(wn * 64 + p * 16 + g2 * 8 + lr) * 128;

    float acc[4][8][4];
#pragma unroll
    for (int mi = 0; mi < 4; mi++)
#pragma unroll
        for (int j = 0; j < 8; j++)
#pragma unroll
            for (int t = 0; t < 4; t++) acc[mi][j][t] = 0.f;

    const int NC = K >> 6;     // 64 halfs per chunk

    // ---- prologue: chunks 0,1 into stages 0,1
#pragma unroll
    for (int s = 0; s < 2; s++) {
        const __half* pa = gA + s * 64;
        const __half* pb = gB + s * 64;
        uint32_t da = sA0 + s * ST_STRIDE;
        uint32_t db = sB0 + s * ST_STRIDE;
#pragma unroll
        for (int i = 0; i < 8; i++) {
            CP16(da + i * 2048, pa + (size_t)i * 16 * K);
            CP16(db + i * 2048, pb + (size_t)i * 16 * K);
        }
        CP_COMMIT();
    }

    for (int c = 0; c < NC; ++c) {
        CP_WAIT1();
        __syncthreads();
        if (c + 2 < NC) {
            const int st = (c + 2) % 3;
            const __half* pa = gA + (size_t)(c + 2) * 64;
            const __half* pb = gB + (size_t)(c + 2) * 64;
            uint32_t da = sA0 + st * ST_STRIDE;
            uint32_t db = sB0 + st * ST_STRIDE;
#pragma unroll
            for (int i = 0; i < 8; i++) {
                CP16(da + i * 2048, pa + (size_t)i * 16 * K);
                CP16(db + i * 2048, pb + (size_t)i * 16 * K);
            }
        }
        CP_COMMIT();

        const uint32_t stOff = (uint32_t)(c % 3) * ST_STRIDE;
#pragma unroll
        for (int s = 0; s < 4; s++) {          // 4 k16-steps per 64-K chunk
            const uint32_t aOff = stOff + ((((uint32_t)(2 * s) + g2) ^ lr) << 4);
            const uint32_t bOff = stOff + ((((uint32_t)(2 * s) + g01) ^ lr) << 4);
            uint32_t af[4][4], bf[4][4];
#pragma unroll
            for (int mi = 0; mi < 4; mi++) ldsm4(af[mi], aRow[mi] + aOff);
#pragma unroll
            for (int p = 0; p < 4; p++)  ldsm4(bf[p], bRow[p] + bOff);
#pragma unroll
            for (int mi = 0; mi < 4; mi++)
#pragma unroll
                for (int p = 0; p < 4; p++) {
                    mma_f16(acc[mi][2 * p],     af[mi], bf[p][0], bf[p][1]);
                    mma_f16(acc[mi][2 * p + 1], af[mi], bf[p][2], bf[p][3]);
                }
        }
    }

    // ---- epilogue
    const int gq = l >> 2, qq = l & 3;
#pragma unroll
    for (int mi = 0; mi < 4; mi++) {
        size_t r1 = row0 + wm * 64 + mi * 16 + gq;
#pragma unroll
        for (int nj = 0; nj < 8; nj++) {
            size_t cc = col0 + wn * 64 + nj * 8 + qq * 2;
            float v00 = acc[mi][nj][0], v01 = acc[mi][nj][1];
            float v10 = acc[mi][nj][2], v11 = acc[mi][nj][3];
            if (EPI == 1) {
                float2 bb = *(const float2*)(bias + cc);
                v00 = silu_f(v00 + bb.x); v01 = silu_f(v01 + bb.y);
                v10 = silu_f(v10 + bb.x); v11 = silu_f(v11 + bb.y);
            }
            if (OUTF == 1) {
                float* C = (float*)Cv;
                *(float2*)(C + r1 * N + cc)       = make_float2(v00, v01);
                *(float2*)(C + (r1 + 8) * N + cc) = make_float2(v10, v11);
            } else {
                __half* C = (__half*)Cv;
                *(__half2*)(C + r1 * N + cc)       = __floats2half2_rn(v00, v01);
                *(__half2*)(C + (r1 + 8) * N + cc) = __floats2half2_rn(v10, v11);
            }
        }
    }
}

// single-GEMM wrapper
template<int EPI, int OUTF>
__global__ void __launch_bounds__(128, 2)
gemm_f16(const __half* __restrict__ A, const __half* __restrict__ B,
         const float* __restrict__ bias, void* __restrict__ Cv,
         int M, int N, int K)
{
    extern __shared__ char smem[];
    gemm_body<EPI, OUTF>(A, B, bias, Cv, M, N, K, smem);
}

// dual-GEMM wrapper: blockIdx.z selects (A,B,bias,C) pair. Both GEMMs share
// M/N/K. Used to fuse the fwd/bwd proj GEMMs into one launch (one tail wave).
template<int EPI, int OUTF>
__global__ void __launch_bounds__(128, 2)
gemm_f16_dual(const __half* __restrict__ A0, const __half* __restrict__ B0,
              const float* __restrict__ bias0, void* __restrict__ C0,
              const __half* __restrict__ A1, const __half* __restrict__ B1,
              const float* __restrict__ bias1, void* __restrict__ C1,
              int M, int N, int K)
{
    extern __shared__ char smem[];
    if (blockIdx.z == 0)
        gemm_body<EPI, OUTF>(A0, B0, bias0, C0, M, N, K, smem);
    else
        gemm_body<EPI, OUTF>(A1, B1, bias1, C1, M, N, K, smem);
}

// ------- merged fp32 -> fp16 convert over 5 segments (one launch) -------------
__global__ void to_half_multi(const float* s0, __half* d0, long long n0,
                              const float* s1, __half* d1, long long n1,
                              const float* s2, __half* d2, long long n2,
                              const float* s3, __half* d3, long long n3,
                              const float* s4, __half* d4, long long n4)
{
    long long i = (long long)blockIdx.x * blockDim.x + threadIdx.x;
    const float* src; __half* dst; long long off = i;
    if (off < n0)      { src = s0; dst = d0; }
    else if ((off -= n0) < n1) { src = s1; dst = d1; }
    else if ((off -= n1) < n2) { src = s2; dst = d2; }
    else if ((off -= n2) < n3) { src = s3; dst = d3; }
    else if ((off -= n3) < n4) { src = s4; dst = d4; }
    else return;
    float4 v = ((const float4*)src)[off];
    __half2* d2p = (__half2*)dst;
    d2p[2 * off]     = __floats2half2_rn(v.x, v.y);
    d2p[2 * off + 1] = __floats2half2_rn(v.z, v.w);
}

// ------- depthwise causal (fwd) + anti-causal (bwd) conv, t-tiled -------------
#define CONV_TT 16
__global__ void conv_dw_tiled(const __half* __restrict__ xz,
                              const float* __restrict__ wf, const float* __restrict__ bf,
                              const float* __restrict__ wb, const float* __restrict__ bb,
                              __half* __restrict__ cf, __half* __restrict__ cb)
{
    const long long id = (long long)blockIdx.x * blockDim.x + threadIdx.x;
    const int c2 = (int)(id & (DIE / 2 - 1));       // half2 channel, warp-contig
    const int c  = c2 * 2;
    const long long tile = id >> 9;                  // DIE/2 = 512 c2 per tile-row
    const long long m0 = tile * CONV_TT;             // global row start
    const int t0 = (int)(m0 & (TD - 1));             // within-sequence start

    const __half2* xz2 = (const __half2*)xz;

    float2 v[CONV_TT + 13];
#pragma unroll
    for (int j = 0; j < CONV_TT + 13; j++) {
        int t = t0 - 6 + j;
        v[j] = make_float2(0.f, 0.f);
        if (t >= 0 && t < TD)
            v[j] = __half22float2(xz2[(m0 - 6 + j) * DIE + c2]);
    }

    float wf0[7], wf1[7], wbr0[7], wbr1[7];
#pragma unroll
    for (int k = 0; k < 7; k++) {
        wf0[k]  = wf[c * 7 + k];
        wf1[k]  = wf[(c + 1) * 7 + k];
        wbr0[k] = wb[c * 7 + (6 - k)];
        wbr1[k] = wb[(c + 1) * 7 + (6 - k)];
    }
    const float bf0 = bf[c], bf1 = bf[c + 1];
    const float bb0 = bb[c], bb1 = bb[c + 1];

    __half2* cf2 = (__half2*)cf;
    __half2* cb2 = (__half2*)cb;
#pragma unroll
    for (int i = 0; i < CONV_TT; i++) {
        float af0 = bf0, af1 = bf1, ab0 = bb0, ab1 = bb1;
#pragma unroll
        for (int k = 0; k < 7; k++) {
            af0 = fmaf(v[i + k].x, wf0[k], af0);
            af1 = fmaf(v[i + k].y, wf1[k], af1);
            ab0 = fmaf(v[i + 7 + k].x, wbr0[k], ab0);
            ab1 = fmaf(v[i + 7 + k].y, wbr1[k], ab1);
        }
        const long long out = (m0 + i) * (DIE / 2) + c2;
        cf2[out] = __floats2half2_rn(af0, af1);
        cb2[out] = __floats2half2_rn(ab0, ab1);
    }
}

// ---------------- combine: shifts + diag + gate, half2 ------------------------
__global__ void combine_k(const __half* __restrict__ xz,
                          const __half* __restrict__ pf, const __half* __restrict__ pb,
                          const float* __restrict__ diag, const float* __restrict__ gate,
                          __half* __restrict__ y)
{
    long long id = (long long)blockIdx.x * blockDim.x + threadIdx.x;  // half2 idx
    int e2 = (int)(id & (DIE / 2 - 1));
    long long m = id >> 9;
    int t = (int)(m & (TD - 1));

    const __half2* pf2 = (const __half2*)pf;
    const __half2* pb2 = (const __half2*)pb;
    const __half2* xz2 = (const __half2*)xz;

    float2 yf = make_float2(0.f, 0.f);
    if (t > 0) yf = __half22float2(pf2[id - DIE / 2]);
    float2 yb = make_float2(0.f, 0.f);
    if (t < TD - 1) yb = __half22float2(pb2[id]);
    float2 xp = __half22float2(xz2[m * DIE + e2]);
    float2 z  = __half22float2(xz2[m * DIE + DIE / 2 + e2]);
    float2 dg = ((const float2*)diag)[e2];
    float gt = gate[0];
    float y0 = (yf.x + yb.x + xp.x * dg.x) * silu_f(z.x) * gt;
    float y1 = (yf.y + yb.y + xp.y * dg.y) * silu_f(z.y) * gt;
    ((__half2*)y)[id] = __floats2half2_rn(y0, y1);
}

// ---------------- residual + LayerNorm(512), o in fp16 ------------------------
__device__ __forceinline__ float warp_sum(float v) {
#pragma unroll
    for (int o = 16; o > 0; o >>= 1) v += __shfl_down_sync(0xffffffffu, v, o);
    return v;
}

__global__ void ln_kernel(const float* __restrict__ x, const __half* __restrict__ o,
                          const float* __restrict__ g, const float* __restrict__ b,
                          float* __restrict__ out)
{
    const int m = blockIdx.x;
    const int tid = threadIdx.x;
    const size_t base = (size_t)m * DD;

    float4 xv = ((const float4*)(x + base))[tid];
    const __half2* o2 = (const __half2*)(o + base);
    float2 oa = __half22float2(o2[tid * 2]);
    float2 ob = __half22float2(o2[tid * 2 + 1]);
    float4 h = make_float4(xv.x + oa.x, xv.y + oa.y, xv.z + ob.x, xv.w + ob.y);

    float s  = h.x + h.y + h.z + h.w;
    float ss = h.x * h.x + h.y * h.y + h.z * h.z + h.w * h.w;

    __shared__ float sh[4], sh2[4];
    float ws  = warp_sum(s);
    float wss = warp_sum(ss);
    if ((tid & 31) == 0) { sh[tid >> 5] = ws; sh2[tid >> 5] = wss; }
    __syncthreads();
    if (tid < 32) {
        float a  = (tid < 4) ? sh[tid]  : 0.f;
        float a2 = (tid < 4) ? sh2[tid] : 0.f;
        a  = warp_sum(a);
        a2 = warp_sum(a2);
        if (tid == 0) { sh[0] = a; sh2[0] = a2; }
    }
    __syncthreads();

    float mu  = sh[0] * (1.f / DD);
    float var = sh2[0] * (1.f / DD) - mu * mu;
    float inv = rsqrtf(var + LN_EPS);

    float4 gv = ((const float4*)g)[tid];
    float4 bv = ((const float4*)b)[tid];
    float4 r;
    r.x = (h.x - mu) * inv * gv.x + bv.x;
    r.y = (h.y - mu) * inv * gv.y + bv.y;
    r.z = (h.z - mu) * inv * gv.z + bv.z;
    r.w = (h.w - mu) * inv * gv.w + bv.w;
    ((float4*)(out + base))[tid] = r;
}

// ---------------- launch ------------------------------------------------------
#define GEMM_SMEM (3 * 32768)   // 96 KB -> 2 CTAs/SM

extern "C" void kernel_launch(void* const* d_in, const int* in_sizes, int n_in,
                              void* d_out, int out_size)
{
    const float* x          = (const float*)d_in[0];
    const float* in_proj_w  = (const float*)d_in[1];
    const float* conv_fwd_w = (const float*)d_in[2];
    const float* conv_fwd_b = (const float*)d_in[3];
    const float* proj_fwd_w = (const float*)d_in[4];
    const float* proj_fwd_b = (const float*)d_in[5];
    const float* conv_bwd_w = (const float*)d_in[6];
    const float* conv_bwd_b = (const float*)d_in[7];
    const float* proj_bwd_w = (const float*)d_in[8];
    const float* proj_bwd_b = (const float*)d_in[9];
    const float* diag       = (const float*)d_in[10];
    const float* gate       = (const float*)d_in[11];
    const float* out_proj_w = (const float*)d_in[12];
    const float* ln_g       = (const float*)d_in[13];
    const float* ln_b       = (const float*)d_in[14];

    __half *xzh, *cfh, *cbh, *pfh, *pbh, *yh, *oh, *xh, *w1h, *wfh, *wbh, *woh;
    cudaGetSymbolAddress((void**)&xzh, g_xzh);
    cudaGetSymbolAddress((void**)&cfh, g_cfh);
    cudaGetSymbolAddress((void**)&cbh, g_cbh);
    cudaGetSymbolAddress((void**)&pfh, g_pfh);
    cudaGetSymbolAddress((void**)&pbh, g_pbh);
    cudaGetSymbolAddress((void**)&yh,  g_yh);
    cudaGetSymbolAddress((void**)&oh,  g_oh);
    cudaGetSymbolAddress((void**)&xh,  g_xh);
    cudaGetSymbolAddress((void**)&w1h, g_w1h);
    cudaGetSymbolAddress((void**)&wfh, g_wfh);
    cudaGetSymbolAddress((void**)&wbh, g_wbh);
    cudaGetSymbolAddress((void**)&woh, g_woh);

    cudaFuncSetAttribute(gemm_f16<0, 0>, cudaFuncAttributeMaxDynamicSharedMemorySize, GEMM_SMEM);
    cudaFuncSetAttribute(gemm_f16_dual<1, 0>, cudaFuncAttributeMaxDynamicSharedMemorySize, GEMM_SMEM);

    // 0) fp16 conversion of x + all weights (single launch)
    {
        const long long n0 = (long long)NROWS * DD / 4;       // x
        const long long n1 = (long long)2 * DIE * DD / 4;     // in_proj_w
        const long long n2 = (long long)DIE * DIE / 4;        // proj_fwd_w
        const long long n3 = (long long)DIE * DIE / 4;        // proj_bwd_w
        const long long n4 = (long long)DD * DIE / 4;         // out_proj_w
        const long long nt = n0 + n1 + n2 + n3 + n4;
        to_half_multi<<<(unsigned)((nt + 255) / 256), 256>>>(
            x, xh, n0, in_proj_w, w1h, n1, proj_fwd_w, wfh, n2,
            proj_bwd_w, wbh, n3, out_proj_w, woh, n4);
    }

    // 1) xz = x @ in_proj_w^T          (32768 x 2048, K=512)
    gemm_f16<0, 0><<<dim3(2048 / 128, NROWS / 128), 128, GEMM_SMEM>>>(
        xh, w1h, nullptr, xzh, NROWS, 2048, DD);
    // 2) both depthwise convs (t-tiled, window in registers)
    conv_dw_tiled<<<(unsigned)(((long long)(NROWS / CONV_TT) * (DIE / 2)) / 256), 256>>>(
        xzh, conv_fwd_w, conv_fwd_b, conv_bwd_w, conv_bwd_b, cfh, cbh);
    // 3+4) pf = silu(cf @ wf^T + b), pb = silu(cb @ wb^T + b) — one launch
    gemm_f16_dual<1, 0><<<dim3(DIE / 128, NROWS / 128, 2), 128, GEMM_SMEM>>>(
        cfh, wfh, proj_fwd_b, pfh,
        cbh, wbh, proj_bwd_b, pbh, NROWS, DIE, DIE);
    // 5) y = (shift(pf) + mask(pb) + x_proj*diag) * silu(z) * gate (half2)
    combine_k<<<(NROWS * DIE / 2) / 256, 256>>>(xzh, pfh, pbh, diag, gate, yh);
    // 6) o = y @ wo^T             (32768 x 512, K=1024), fp16 out
    gemm_f16<0, 0><<<dim3(DD / 128, NROWS / 128), 128, GEMM_SMEM>>>(
        yh, woh, nullptr, oh, NROWS, DD, DIE);
    // 7) out = LayerNorm(x + o)
    ln_kernel<<<NROWS, 128>>>(x, oh, ln_g, ln_b, (float*)d_out);
}

// round 16
// speedup vs baseline: 1.3631x; 1.0745x over previous
#include <cuda_runtime.h>
#include <cuda_fp16.h>
#include <cstdint>

// Problem constants
#define BD    8
#define TD    4096
#define DD    512
#define DIE   1024          // DI
#define NROWS (BD*TD)       // 32768
#define LN_EPS 1e-5f

// ---------------- scratch (no cudaMalloc allowed) ----------------
__device__ __half g_xzh[(size_t)NROWS * 2 * DIE];   // gemm1 out (fp16)
__device__ __half g_cfh[(size_t)NROWS * DIE];
__device__ __half g_cbh[(size_t)NROWS * DIE];
__device__ __half g_pfh[(size_t)NROWS * DIE];
__device__ __half g_pbh[(size_t)NROWS * DIE];
__device__ __half g_yh [(size_t)NROWS * DIE];
__device__ __half g_oh [(size_t)NROWS * DD];        // out_proj result (fp16)
__device__ __half g_xh [(size_t)NROWS * DD];        // fp16 x
__device__ __half g_w1h[(size_t)2 * DIE * DD];
__device__ __half g_wfh[(size_t)DIE * DIE];
__device__ __half g_wbh[(size_t)DIE * DIE];
__device__ __half g_woh[(size_t)DD * DIE];

__device__ __forceinline__ float silu_f(float v) {
    return v / (1.f + __expf(-v));
}

__device__ __forceinline__ uint32_t smem_to_u32(const void* p) {
    uint32_t a;
    asm("{ .reg .u64 t; cvta.to.shared.u64 t, %1; cvt.u32.u64 %0, t; }" : "=r"(a) : "l"(p));
    return a;
}

__device__ __forceinline__ void mma_f16(float* c, const uint32_t* a,
                                        uint32_t b0, uint32_t b1) {
    asm volatile(
        "mma.sync.aligned.m16n8k16.row.col.f32.f16.f16.f32 "
        "{%0,%1,%2,%3}, {%4,%5,%6,%7}, {%8,%9}, {%0,%1,%2,%3};"
        : "+f"(c[0]), "+f"(c[1]), "+f"(c[2]), "+f"(c[3])
        : "r"(a[0]), "r"(a[1]), "r"(a[2]), "r"(a[3]), "r"(b0), "r"(b1));
}

__device__ __forceinline__ void ldsm4(uint32_t* r, uint32_t addr) {
    asm volatile("ldmatrix.sync.aligned.m8n8.x4.shared.b16 {%0,%1,%2,%3}, [%4];"
        : "=r"(r[0]), "=r"(r[1]), "=r"(r[2]), "=r"(r[3]) : "r"(addr));
}

#define CP16(dst, src) \
    asm volatile("cp.async.cg.shared.global [%0], [%1], 16;" :: "r"(dst), "l"(src))
#define CP_COMMIT() asm volatile("cp.async.commit_group;" ::: "memory")
#define CP_WAIT1()  asm volatile("cp.async.wait_group 1;" ::: "memory")

// ====== fp16 GEMM core (device func): C[M,N] = A[M,K]*B[N,K]^T, fp32 acc =====
// 128x128x64 CTA tile, 128 threads, 4 warps (2M x 2N), warp tile 64x64.
// 3-stage cp.async pipeline (stage = A 16KB + B 16KB), 2 CTAs/SM.
// EPI==0: C = acc   EPI==1: C = silu(acc + bias[n])
// OUTF==0: __half   OUTF==1: float
#define ST_STRIDE 32768u
template<int EPI, int OUTF>
__device__ __forceinline__ void gemm_body(
        const __half* __restrict__ A, const __half* __restrict__ B,
        const float* __restrict__ bias, void* __restrict__ Cv,
        int M, int N, int K, char* smem)
{
    const uint32_t al = smem_to_u32(smem);

    const int tid = threadIdx.x;
    const int wid = tid >> 5, l = tid & 31;
    const int wm = wid >> 1, wn = wid & 1;

    const size_t row0 = (size_t)blockIdx.y * 128;
    const size_t col0 = (size_t)blockIdx.x * 128;

    // ---- cp.async invariants: thread -> (row = tid>>3 + 16i, 16B-group = tid&7)
    const int ldr = tid >> 3;        // 0..15
    const int ldkg = tid & 7;
    const uint32_t sg = (uint32_t)(ldkg ^ (ldr & 7)) << 4;
    const __half* gA = A + (row0 + ldr) * (size_t)K + ldkg * 8;
    const __half* gB = B + (col0 + ldr) * (size_t)K + ldkg * 8;
    const uint32_t sA0 = al + ldr * 128 + sg;
    const uint32_t sB0 = al + 16384 + ldr * 128 + sg;

    // ---- fragment address invariants
    const uint32_t lr = l & 7, g01 = (l >> 3) & 1, g2 = (uint32_t)l >> 4;
    uint32_t aRow[4], bRow[4];
#pragma unroll
    for (int mi = 0; mi < 4; mi++)
        aRow[mi] = al + (uint32_t)(wm * 64 + mi * 16 + g01 * 8 + lr) * 128;
#pragma unroll
    for (int p = 0; p < 4; p++)
        bRow[p] = al + 16384 + (uint32_t)(wn * 64 + p * 16 + g2 * 8 + lr) * 128;

    float acc[4][8][4];
#pragma unroll
    for (int mi = 0; mi < 4; mi++)
#pragma unroll
        for (int j = 0; j < 8; j++)
#pragma unroll
            for (int t = 0; t < 4; t++) acc[mi][j][t] = 0.f;

    const int NC = K >> 6;     // 64 halfs per chunk

    // ---- prologue: chunks 0,1 into stages 0,1
#pragma unroll
    for (int s = 0; s < 2; s++) {
        const __half* pa = gA + s * 64;
        const __half* pb = gB + s * 64;
        uint32_t da = sA0 + s * ST_STRIDE;
        uint32_t db = sB0 + s * ST_STRIDE;
#pragma unroll
        for (int i = 0; i < 8; i++) {
            CP16(da + i * 2048, pa + (size_t)i * 16 * K);
            CP16(db + i * 2048, pb + (size_t)i * 16 * K);
        }
        CP_COMMIT();
    }

    for (int c = 0; c < NC; ++c) {
        CP_WAIT1();
        __syncthreads();
        if (c + 2 < NC) {
            const int st = (c + 2) % 3;
            const __half* pa = gA + (size_t)(c + 2) * 64;
            const __half* pb = gB + (size_t)(c + 2) * 64;
            uint32_t da = sA0 + st * ST_STRIDE;
            uint32_t db = sB0 + st * ST_STRIDE;
#pragma unroll
            for (int i = 0; i < 8; i++) {
                CP16(da + i * 2048, pa + (size_t)i * 16 * K);
                CP16(db + i * 2048, pb + (size_t)i * 16 * K);
            }
        }
        CP_COMMIT();

        const uint32_t stOff = (uint32_t)(c % 3) * ST_STRIDE;
#pragma unroll
        for (int s = 0; s < 4; s++) {          // 4 k16-steps per 64-K chunk
            const uint32_t aOff = stOff + ((((uint32_t)(2 * s) + g2) ^ lr) << 4);
            const uint32_t bOff = stOff + ((((uint32_t)(2 * s) + g01) ^ lr) << 4);
            uint32_t af[4][4], bf[4][4];
#pragma unroll
            for (int mi = 0; mi < 4; mi++) ldsm4(af[mi], aRow[mi] + aOff);
#pragma unroll
            for (int p = 0; p < 4; p++)  ldsm4(bf[p], bRow[p] + bOff);
#pragma unroll
            for (int mi = 0; mi < 4; mi++)
#pragma unroll
                for (int p = 0; p < 4; p++) {
                    mma_f16(acc[mi][2 * p],     af[mi], bf[p][0], bf[p][1]);
                    mma_f16(acc[mi][2 * p + 1], af[mi], bf[p][2], bf[p][3]);
                }
        }
    }

    // ---- epilogue
    const int gq = l >> 2, qq = l & 3;
#pragma unroll
    for (int mi = 0; mi < 4; mi++) {
        size_t r1 = row0 + wm * 64 + mi * 16 + gq;
#pragma unroll
        for (int nj = 0; nj < 8; nj++) {
            size_t cc = col0 + wn * 64 + nj * 8 + qq * 2;
            float v00 = acc[mi][nj][0], v01 = acc[mi][nj][1];
            float v10 = acc[mi][nj][2], v11 = acc[mi][nj][3];
            if (EPI == 1) {
                float2 bb = *(const float2*)(bias + cc);
                v00 = silu_f(v00 + bb.x); v01 = silu_f(v01 + bb.y);
                v10 = silu_f(v10 + bb.x); v11 = silu_f(v11 + bb.y);
            }
            if (OUTF == 1) {
                float* C = (float*)Cv;
                *(float2*)(C + r1 * N + cc)       = make_float2(v00, v01);
                *(float2*)(C + (r1 + 8) * N + cc) = make_float2(v10, v11);
            } else {
                __half* C = (__half*)Cv;
                *(__half2*)(C + r1 * N + cc)       = __floats2half2_rn(v00, v01);
                *(__half2*)(C + (r1 + 8) * N + cc) = __floats2half2_rn(v10, v11);
            }
        }
    }
}

// single-GEMM wrapper
template<int EPI, int OUTF>
__global__ void __launch_bounds__(128, 2)
gemm_f16(const __half* __restrict__ A, const __half* __restrict__ B,
         const float* __restrict__ bias, void* __restrict__ Cv,
         int M, int N, int K)
{
    extern __shared__ char smem[];
    gemm_body<EPI, OUTF>(A, B, bias, Cv, M, N, K, smem);
}

// dual-GEMM wrapper: blockIdx.z selects (A,B,bias,C) pair. Both GEMMs share
// M/N/K. Fuses the fwd/bwd proj GEMMs into one launch (one tail wave).
template<int EPI, int OUTF>
__global__ void __launch_bounds__(128, 2)
gemm_f16_dual(const __half* __restrict__ A0, const __half* __restrict__ B0,
              const float* __restrict__ bias0, void* __restrict__ C0,
              const __half* __restrict__ A1, const __half* __restrict__ B1,
              const float* __restrict__ bias1, void* __restrict__ C1,
              int M, int N, int K)
{
    extern __shared__ char smem[];
    if (blockIdx.z == 0)
        gemm_body<EPI, OUTF>(A0, B0, bias0, C0, M, N, K, smem);
    else
        gemm_body<EPI, OUTF>(A1, B1, bias1, C1, M, N, K, smem);
}

// ------- merged fp32 -> fp16 convert over 5 segments (one launch) -------------
__global__ void to_half_multi(const float* s0, __half* d0, long long n0,
                              const float* s1, __half* d1, long long n1,
                              const float* s2, __half* d2, long long n2,
                              const float* s3, __half* d3, long long n3,
                              const float* s4, __half* d4, long long n4)
{
    long long i = (long long)blockIdx.x * blockDim.x + threadIdx.x;
    const float* src; __half* dst; long long off = i;
    if (off < n0)      { src = s0; dst = d0; }
    else if ((off -= n0) < n1) { src = s1; dst = d1; }
    else if ((off -= n1) < n2) { src = s2; dst = d2; }
    else if ((off -= n2) < n3) { src = s3; dst = d3; }
    else if ((off -= n3) < n4) { src = s4; dst = d4; }
    else return;
    float4 v = ((const float4*)src)[off];
    __half2* d2p = (__half2*)dst;
    d2p[2 * off]     = __floats2half2_rn(v.x, v.y);
    d2p[2 * off + 1] = __floats2half2_rn(v.z, v.w);
}

// ------- depthwise causal (fwd) + anti-causal (bwd) conv, t-tiled -------------
#define CONV_TT 16
__global__ void conv_dw_tiled(const __half* __restrict__ xz,
                              const float* __restrict__ wf, const float* __restrict__ bf,
                              const float* __restrict__ wb, const float* __restrict__ bb,
                              __half* __restrict__ cf, __half* __restrict__ cb)
{
    const long long id = (long long)blockIdx.x * blockDim.x + threadIdx.x;
    const int c2 = (int)(id & (DIE / 2 - 1));       // half2 channel, warp-contig
    const int c  = c2 * 2;
    const long long tile = id >> 9;                  // DIE/2 = 512 c2 per tile-row
    const long long m0 = tile * CONV_TT;             // global row start
    const int t0 = (int)(m0 & (TD - 1));             // within-sequence start

    const __half2* xz2 = (const __half2*)xz;

    float2 v[CONV_TT + 13];
#pragma unroll
    for (int j = 0; j < CONV_TT + 13; j++) {
        int t = t0 - 6 + j;
        v[j] = make_float2(0.f, 0.f);
        if (t >= 0 && t < TD)
            v[j] = __half22float2(xz2[(m0 - 6 + j) * DIE + c2]);
    }

    float wf0[7], wf1[7], wbr0[7], wbr1[7];
#pragma unroll
    for (int k = 0; k < 7; k++) {
        wf0[k]  = wf[c * 7 + k];
        wf1[k]  = wf[(c + 1) * 7 + k];
        wbr0[k] = wb[c * 7 + (6 - k)];
        wbr1[k] = wb[(c + 1) * 7 + (6 - k)];
    }
    const float bf0 = bf[c], bf1 = bf[c + 1];
    const float bb0 = bb[c], bb1 = bb[c + 1];

    __half2* cf2 = (__half2*)cf;
    __half2* cb2 = (__half2*)cb;
#pragma unroll
    for (int i = 0; i < CONV_TT; i++) {
        float af0 = bf0, af1 = bf1, ab0 = bb0, ab1 = bb1;
#pragma unroll
        for (int k = 0; k < 7; k++) {
            af0 = fmaf(v[i + k].x, wf0[k], af0);
            af1 = fmaf(v[i + k].y, wf1[k], af1);
            ab0 = fmaf(v[i + 7 + k].x, wbr0[k], ab0);
            ab1 = fmaf(v[i + 7 + k].y, wbr1[k], ab1);
        }
        const long long out = (m0 + i) * (DIE / 2) + c2;
        cf2[out] = __floats2half2_rn(af0, af1);
        cb2[out] = __floats2half2_rn(ab0, ab1);
    }
}

// -------- combine: shifts + diag + gate, uint2 (4 halfs / thread) -------------
__global__ void combine_k4(const __half* __restrict__ xz,
                           const __half* __restrict__ pf, const __half* __restrict__ pb,
                           const float* __restrict__ diag, const float* __restrict__ gate,
                           __half* __restrict__ y)
{
    long long id = (long long)blockIdx.x * blockDim.x + threadIdx.x;  // uint2 idx
    int e4 = (int)(id & (DIE / 4 - 1));       // 4-half group within row
    long long m = id >> 8;                    // DIE/4 = 256 groups per row
    int t = (int)(m & (TD - 1));

    const uint2* pf4 = (const uint2*)pf;
    const uint2* pb4 = (const uint2*)pb;
    const uint2* xz4 = (const uint2*)xz;

    uint2 zero2 = make_uint2(0u, 0u);
    uint2 yfu = (t > 0)      ? pf4[id - DIE / 4] : zero2;
    uint2 ybu = (t < TD - 1) ? pb4[id]           : zero2;
    uint2 xpu = xz4[m * (DIE / 2) + e4];
    uint2 zu  = xz4[m * (DIE / 2) + DIE / 4 + e4];
    float4 dg = ((const float4*)diag)[e4];
    float gt = gate[0];

    float2 yf0 = __half22float2(*(const __half2*)&yfu.x);
    float2 yf1 = __half22float2(*(const __half2*)&yfu.y);
    float2 yb0 = __half22float2(*(const __half2*)&ybu.x);
    float2 yb1 = __half22float2(*(const __half2*)&ybu.y);
    float2 xp0 = __half22float2(*(const __half2*)&xpu.x);
    float2 xp1 = __half22float2(*(const __half2*)&xpu.y);
    float2 z0  = __half22float2(*(const __half2*)&zu.x);
    float2 z1  = __half22float2(*(const __half2*)&zu.y);

    float r0 = (yf0.x + yb0.x + xp0.x * dg.x) * silu_f(z0.x) * gt;
    float r1 = (yf0.y + yb0.y + xp0.y * dg.y) * silu_f(z0.y) * gt;
    float r2 = (yf1.x + yb1.x + xp1.x * dg.z) * silu_f(z1.x) * gt;
    float r3 = (yf1.y + yb1.y + xp1.y * dg.w) * silu_f(z1.y) * gt;

    uint2 out;
    *(__half2*)&out.x = __floats2half2_rn(r0, r1);
    *(__half2*)&out.y = __floats2half2_rn(r2, r3);
    ((uint2*)y)[id] = out;
}

// ---------------- residual + LayerNorm(512), o in fp16 ------------------------
__device__ __forceinline__ float warp_sum(float v) {
#pragma unroll
    for (int o = 16; o > 0; o >>= 1) v += __shfl_down_sync(0xffffffffu, v, o);
    return v;
}

__global__ void ln_kernel(const float* __restrict__ x, const __half* __restrict__ o,
                          const float* __restrict__ g, const float* __restrict__ b,
                          float* __restrict__ out)
{
    const int m = blockIdx.x;
    const int tid = threadIdx.x;
    const size_t base = (size_t)m * DD;

    float4 xv = ((const float4*)(x + base))[tid];
    const __half2* o2 = (const __half2*)(o + base);
    float2 oa = __half22float2(o2[tid * 2]);
    float2 ob = __half22float2(o2[tid * 2 + 1]);
    float4 h = make_float4(xv.x + oa.x, xv.y + oa.y, xv.z + ob.x, xv.w + ob.y);

    float s  = h.x + h.y + h.z + h.w;
    float ss = h.x * h.x + h.y * h.y + h.z * h.z + h.w * h.w;

    __shared__ float sh[4], sh2[4];
    float ws  = warp_sum(s);
    float wss = warp_sum(ss);
    if ((tid & 31) == 0) { sh[tid >> 5] = ws; sh2[tid >> 5] = wss; }
    __syncthreads();
    if (tid < 32) {
        float a  = (tid < 4) ? sh[tid]  : 0.f;
        float a2 = (tid < 4) ? sh2[tid] : 0.f;
        a  = warp_sum(a);
        a2 = warp_sum(a2);
        if (tid == 0) { sh[0] = a; sh2[0] = a2; }
    }
    __syncthreads();

    float mu  = sh[0] * (1.f / DD);
    float var = sh2[0] * (1.f / DD) - mu * mu;
    float inv = rsqrtf(var + LN_EPS);

    float4 gv = ((const float4*)g)[tid];
    float4 bv = ((const float4*)b)[tid];
    float4 r;
    r.x = (h.x - mu) * inv * gv.x + bv.x;
    r.y = (h.y - mu) * inv * gv.y + bv.y;
    r.z = (h.z - mu) * inv * gv.z + bv.z;
    r.w = (h.w - mu) * inv * gv.w + bv.w;
    ((float4*)(out + base))[tid] = r;
}

// ---------------- launch ------------------------------------------------------
#define GEMM_SMEM (3 * 32768)   // 96 KB -> 2 CTAs/SM

extern "C" void kernel_launch(void* const* d_in, const int* in_sizes, int n_in,
                              void* d_out, int out_size)
{
    const float* x          = (const float*)d_in[0];
    const float* in_proj_w  = (const float*)d_in[1];
    const float* conv_fwd_w = (const float*)d_in[2];
    const float* conv_fwd_b = (const float*)d_in[3];
    const float* proj_fwd_w = (const float*)d_in[4];
    const float* proj_fwd_b = (const float*)d_in[5];
    const float* conv_bwd_w = (const float*)d_in[6];
    const float* conv_bwd_b = (const float*)d_in[7];
    const float* proj_bwd_w = (const float*)d_in[8];
    const float* proj_bwd_b = (const float*)d_in[9];
    const float* diag       = (const float*)d_in[10];
    const float* gate       = (const float*)d_in[11];
    const float* out_proj_w = (const float*)d_in[12];
    const float* ln_g       = (const float*)d_in[13];
    const float* ln_b       = (const float*)d_in[14];

    __half *xzh, *cfh, *cbh, *pfh, *pbh, *yh, *oh, *xh, *w1h, *wfh, *wbh, *woh;
    cudaGetSymbolAddress((void**)&xzh, g_xzh);
    cudaGetSymbolAddress((void**)&cfh, g_cfh);
    cudaGetSymbolAddress((void**)&cbh, g_cbh);
    cudaGetSymbolAddress((void**)&pfh, g_pfh);
    cudaGetSymbolAddress((void**)&pbh, g_pbh);
    cudaGetSymbolAddress((void**)&yh,  g_yh);
    cudaGetSymbolAddress((void**)&oh,  g_oh);
    cudaGetSymbolAddress((void**)&xh,  g_xh);
    cudaGetSymbolAddress((void**)&w1h, g_w1h);
    cudaGetSymbolAddress((void**)&wfh, g_wfh);
    cudaGetSymbolAddress((void**)&wbh, g_wbh);
    cudaGetSymbolAddress((void**)&woh, g_woh);

    cudaFuncSetAttribute(gemm_f16<0, 0>, cudaFuncAttributeMaxDynamicSharedMemorySize, GEMM_SMEM);
    cudaFuncSetAttribute(gemm_f16_dual<1, 0>, cudaFuncAttributeMaxDynamicSharedMemorySize, GEMM_SMEM);

    // 0) fp16 conversion of x + all weights (single launch)
    {
        const long long n0 = (long long)NROWS * DD / 4;       // x
        const long long n1 = (long long)2 * DIE * DD / 4;     // in_proj_w
        const long long n2 = (long long)DIE * DIE / 4;        // proj_fwd_w
        const long long n3 = (long long)DIE * DIE / 4;        // proj_bwd_w
        const long long n4 = (long long)DD * DIE / 4;         // out_proj_w
        const long long nt = n0 + n1 + n2 + n3 + n4;
        to_half_multi<<<(unsigned)((nt + 255) / 256), 256>>>(
            x, xh, n0, in_proj_w, w1h, n1, proj_fwd_w, wfh, n2,
            proj_bwd_w, wbh, n3, out_proj_w, woh, n4);
    }

    // 1) xz = x @ in_proj_w^T          (32768 x 2048, K=512)
    gemm_f16<0, 0><<<dim3(2048 / 128, NROWS / 128), 128, GEMM_SMEM>>>(
        xh, w1h, nullptr, xzh, NROWS, 2048, DD);
    // 2) both depthwise convs (t-tiled, window in registers)
    conv_dw_tiled<<<(unsigned)(((long long)(NROWS / CONV_TT) * (DIE / 2)) / 256), 256>>>(
        xzh, conv_fwd_w, conv_fwd_b, conv_bwd_w, conv_bwd_b, cfh, cbh);
    // 3+4) pf = silu(cf @ wf^T + b), pb = silu(cb @ wb^T + b) — one launch
    gemm_f16_dual<1, 0><<<dim3(DIE / 128, NROWS / 128, 2), 128, GEMM_SMEM>>>(
        cfh, wfh, proj_fwd_b, pfh,
        cbh, wbh, proj_bwd_b, pbh, NROWS, DIE, DIE);
    // 5) y = (shift(pf) + mask(pb) + x_proj*diag) * silu(z) * gate (uint2)
    combine_k4<<<(NROWS * DIE / 4) / 256, 256>>>(xzh, pfh, pbh, diag, gate, yh);
    // 6) o = y @ wo^T             (32768 x 512, K=1024), fp16 out
    gemm_f16<0, 0><<<dim3(DD / 128, NROWS / 128), 128, GEMM_SMEM>>>(
        yh, woh, nullptr, oh, NROWS, DD, DIE);
    // 7) out = LayerNorm(x + o)
    ln_kernel<<<NROWS, 128>>>(x, oh, ln_g, ln_b, (float*)d_out);
}